// round 1
// baseline (speedup 1.0000x reference)
#include <cuda_runtime.h>
#include <cuda_bf16.h>
#include <math.h>

// ---------------- problem constants ----------------
#define SEQ   2048
#define DIMC  1024
#define HEADS 16
#define KVH   4
#define HD    64
#define KVDIM 256     // KVH*HD
#define WIN   64
#define NGLOB 32      // SEQ/WIN
#define TQ    32      // queries per attention block
#define SCALE 0.125f  // HD^-0.5

// ---------------- scratch (no allocation allowed) ----------------
__device__ float g_Q[SEQ * DIMC];     // 8 MB
__device__ float g_K[SEQ * KVDIM];    // 2 MB
__device__ float g_V[SEQ * KVDIM];    // 2 MB
__device__ float g_A[SEQ * DIMC];     // 8 MB  (attention output, pre-Wo)

// =================================================================
// Classic SGEMM: C[M,N] = A[M,K] @ B[K,N], all row-major.
// BM=128, BN=128, BK=8, 256 threads, 8x8 per-thread microtile.
// M,N,K all divisible by tile dims for our shapes.
// =================================================================
__global__ __launch_bounds__(256, 2)
void sgemm128(const float* __restrict__ A, const float* __restrict__ B,
              float* __restrict__ C, int M, int N, int K)
{
    __shared__ float As[8][132];   // transposed A tile, padded
    __shared__ float Bs[8][128];

    const int bx = blockIdx.x;     // N tile
    const int by = blockIdx.y;     // M tile
    const int tid = threadIdx.x;

    const int arow = tid >> 1;             // 0..127
    const int acol = (tid & 1) * 4;        // 0 or 4
    const int brow = tid >> 5;             // 0..7
    const int bcol = (tid & 31) * 4;       // 0..124

    const int tx = (tid & 15) * 8;
    const int ty = (tid >> 4) * 8;

    float acc[8][8];
#pragma unroll
    for (int i = 0; i < 8; i++)
#pragma unroll
        for (int j = 0; j < 8; j++) acc[i][j] = 0.f;

    const float* Aptr = A + (size_t)(by * 128 + arow) * K + acol;
    const float* Bptr = B + (size_t)brow * N + bx * 128 + bcol;

    for (int k0 = 0; k0 < K; k0 += 8) {
        float4 av = *(const float4*)(Aptr + k0);
        As[acol + 0][arow] = av.x;
        As[acol + 1][arow] = av.y;
        As[acol + 2][arow] = av.z;
        As[acol + 3][arow] = av.w;
        float4 bv = *(const float4*)(Bptr + (size_t)k0 * N);
        *(float4*)&Bs[brow][bcol] = bv;
        __syncthreads();
#pragma unroll
        for (int kk = 0; kk < 8; kk++) {
            float a[8], b[8];
            *(float4*)&a[0] = *(const float4*)&As[kk][ty];
            *(float4*)&a[4] = *(const float4*)&As[kk][ty + 4];
            *(float4*)&b[0] = *(const float4*)&Bs[kk][tx];
            *(float4*)&b[4] = *(const float4*)&Bs[kk][tx + 4];
#pragma unroll
            for (int i = 0; i < 8; i++)
#pragma unroll
                for (int j = 0; j < 8; j++)
                    acc[i][j] = fmaf(a[i], b[j], acc[i][j]);
        }
        __syncthreads();
    }

    float* Cptr = C + (size_t)(by * 128 + ty) * N + bx * 128 + tx;
#pragma unroll
    for (int i = 0; i < 8; i++) {
        *(float4*)(Cptr + (size_t)i * N)     = make_float4(acc[i][0], acc[i][1], acc[i][2], acc[i][3]);
        *(float4*)(Cptr + (size_t)i * N + 4) = make_float4(acc[i][4], acc[i][5], acc[i][6], acc[i][7]);
    }
}

// =================================================================
// Fused QKV GEMM: logical N = 1024 + 256 + 256 = 1536 -> 12 column tiles.
// bx 0..7 -> Wq/g_Q, bx 8..9 -> Wk/g_K, bx 10..11 -> Wv/g_V.
// Grid (12, 16) = 192 blocks.
// =================================================================
__global__ __launch_bounds__(256, 2)
void sgemm_qkv(const float* __restrict__ A,
               const float* __restrict__ Wq, const float* __restrict__ Wk,
               const float* __restrict__ Wv,
               float* __restrict__ Q, float* __restrict__ Ko, float* __restrict__ Vo)
{
    __shared__ float As[8][132];
    __shared__ float Bs[8][128];

    const int bx = blockIdx.x;
    const int by = blockIdx.y;
    const int tid = threadIdx.x;
    const int K = DIMC;

    const float* B; float* C; int Nb; int bcol0;
    if (bx < 8)       { B = Wq; C = Q;  Nb = DIMC;  bcol0 = bx * 128; }
    else if (bx < 10) { B = Wk; C = Ko; Nb = KVDIM; bcol0 = (bx - 8) * 128; }
    else              { B = Wv; C = Vo; Nb = KVDIM; bcol0 = (bx - 10) * 128; }

    const int arow = tid >> 1;
    const int acol = (tid & 1) * 4;
    const int brow = tid >> 5;
    const int bcol = (tid & 31) * 4;
    const int tx = (tid & 15) * 8;
    const int ty = (tid >> 4) * 8;

    float acc[8][8];
#pragma unroll
    for (int i = 0; i < 8; i++)
#pragma unroll
        for (int j = 0; j < 8; j++) acc[i][j] = 0.f;

    const float* Aptr = A + (size_t)(by * 128 + arow) * K + acol;
    const float* Bptr = B + (size_t)brow * Nb + bcol0 + bcol;

    for (int k0 = 0; k0 < K; k0 += 8) {
        float4 av = *(const float4*)(Aptr + k0);
        As[acol + 0][arow] = av.x;
        As[acol + 1][arow] = av.y;
        As[acol + 2][arow] = av.z;
        As[acol + 3][arow] = av.w;
        float4 bv = *(const float4*)(Bptr + (size_t)k0 * Nb);
        *(float4*)&Bs[brow][bcol] = bv;
        __syncthreads();
#pragma unroll
        for (int kk = 0; kk < 8; kk++) {
            float a[8], b[8];
            *(float4*)&a[0] = *(const float4*)&As[kk][ty];
            *(float4*)&a[4] = *(const float4*)&As[kk][ty + 4];
            *(float4*)&b[0] = *(const float4*)&Bs[kk][tx];
            *(float4*)&b[4] = *(const float4*)&Bs[kk][tx + 4];
#pragma unroll
            for (int i = 0; i < 8; i++)
#pragma unroll
                for (int j = 0; j < 8; j++)
                    acc[i][j] = fmaf(a[i], b[j], acc[i][j]);
        }
        __syncthreads();
    }

    float* Cptr = C + (size_t)(by * 128 + ty) * Nb + bcol0 + tx;
#pragma unroll
    for (int i = 0; i < 8; i++) {
        *(float4*)(Cptr + (size_t)i * Nb)     = make_float4(acc[i][0], acc[i][1], acc[i][2], acc[i][3]);
        *(float4*)(Cptr + (size_t)i * Nb + 4) = make_float4(acc[i][4], acc[i][5], acc[i][6], acc[i][7]);
    }
}

// =================================================================
// Attention: one block per (head, 32-query tile). Grid (64, 16), 256 thr.
// Local banded-causal softmax with ALiBi + global strided softmax; outputs added.
// =================================================================
__global__ __launch_bounds__(256)
void attn_kernel(const float* __restrict__ Q, const float* __restrict__ K,
                 const float* __restrict__ V, float* __restrict__ O)
{
    __shared__ float Qs[TQ][HD];              // 8 KB; reused as Vg[NGLOB][HD]
    __shared__ float Ks[TQ + WIN][HD + 1];    // 96x65 padded; reused as Vl
    __shared__ float Sl[TQ][WIN + 1];         // local scores (65/row); also Kg staging
    __shared__ float Sg[TQ][NGLOB];           // global scores

    const int h    = blockIdx.y;
    const int kvh  = h >> 2;                  // HEADS/KVH = 4
    const int q0   = blockIdx.x * TQ;
    const int tid  = threadIdx.x;
    const float slope = exp2f(-0.5f * (float)(h + 1));

    // ---- stage Q tile, local K window, global K (into Sl region, stride 65) ----
    for (int i = tid; i < TQ * HD; i += 256) {
        int q = i >> 6, d = i & 63;
        Qs[q][d] = Q[(size_t)(q0 + q) * DIMC + h * HD + d];
    }
    for (int i = tid; i < (TQ + WIN) * HD; i += 256) {
        int r = i >> 6, d = i & 63;
        int key = q0 - WIN + r;
        Ks[r][d] = (key >= 0) ? K[(size_t)key * KVDIM + kvh * HD + d] : 0.f;
    }
    for (int i = tid; i < NGLOB * HD; i += 256) {
        int g = i >> 6, d = i & 63;
        Sl[g][d] = K[(size_t)(g * WIN) * KVDIM + kvh * HD + d];   // Kg staged in Sl
    }
    __syncthreads();

    // ---- global scores (reads Kg from Sl region) ----
    for (int it = tid; it < TQ * NGLOB; it += 256) {
        int q = it >> 5, g = it & 31;
        float s = 0.f;
#pragma unroll
        for (int d = 0; d < HD; d++) s = fmaf(Qs[q][d], Sl[g][d], s);
        Sg[q][g] = s * SCALE;
    }
    __syncthreads();

    // ---- local scores (overwrites Sl) ----
    for (int it = tid; it < TQ * (WIN + 1); it += 256) {
        int q = it / (WIN + 1);
        int j = it - q * (WIN + 1);       // 0..64
        int key = q0 + q - WIN + j;
        float s = -3.0e38f;
        if (key >= 0) {
            float acc = 0.f;
#pragma unroll
            for (int d = 0; d < HD; d++) acc = fmaf(Qs[q][d], Ks[q + j][d], acc);
            s = acc * SCALE + (float)(j - WIN) * slope;
        }
        Sl[q][j] = s;
    }
    __syncthreads();

    // ---- two softmaxes, warp per 4 rows ----
    {
        const int warp = tid >> 5, lane = tid & 31;
        for (int q = warp * 4; q < warp * 4 + 4; q++) {
            // local (65 entries)
            float m = -3.0e38f;
            for (int j = lane; j < WIN + 1; j += 32) m = fmaxf(m, Sl[q][j]);
#pragma unroll
            for (int o = 16; o; o >>= 1) m = fmaxf(m, __shfl_xor_sync(~0u, m, o));
            float sum = 0.f;
            for (int j = lane; j < WIN + 1; j += 32) {
                float e = __expf(Sl[q][j] - m);
                Sl[q][j] = e;
                sum += e;
            }
#pragma unroll
            for (int o = 16; o; o >>= 1) sum += __shfl_xor_sync(~0u, sum, o);
            float inv = 1.f / sum;
            for (int j = lane; j < WIN + 1; j += 32) Sl[q][j] *= inv;
            // global (32 entries, unmasked)
            float gv = Sg[q][lane];
            float mg = gv;
#pragma unroll
            for (int o = 16; o; o >>= 1) mg = fmaxf(mg, __shfl_xor_sync(~0u, mg, o));
            float e = __expf(gv - mg);
            float sg = e;
#pragma unroll
            for (int o = 16; o; o >>= 1) sg += __shfl_xor_sync(~0u, sg, o);
            Sg[q][lane] = e / sg;
        }
    }
    __syncthreads();

    // ---- reload V into Ks (local window) and Qs (global rows) ----
    for (int i = tid; i < (TQ + WIN) * HD; i += 256) {
        int r = i >> 6, d = i & 63;
        int key = q0 - WIN + r;
        Ks[r][d] = (key >= 0) ? V[(size_t)key * KVDIM + kvh * HD + d] : 0.f;
    }
    for (int i = tid; i < NGLOB * HD; i += 256) {
        int g = i >> 6, d = i & 63;
        Qs[g][d] = V[(size_t)(g * WIN) * KVDIM + kvh * HD + d];
    }
    __syncthreads();

    // ---- PV: out[q][d] = sum_j pl*Vl + sum_g pg*Vg ----
    for (int it = tid; it < TQ * HD; it += 256) {
        int q = it >> 6, d = it & 63;
        float acc = 0.f;
#pragma unroll
        for (int j = 0; j < WIN + 1; j++) acc = fmaf(Sl[q][j], Ks[q + j][d], acc);
#pragma unroll
        for (int g = 0; g < NGLOB; g++) acc = fmaf(Sg[q][g], Qs[g][d], acc);
        O[(size_t)(q0 + q) * DIMC + h * HD + d] = acc;
    }
}

// =================================================================
extern "C" void kernel_launch(void* const* d_in, const int* in_sizes, int n_in,
                              void* d_out, int out_size)
{
    const float* x  = (const float*)d_in[0];
    const float* Wq = (const float*)d_in[1];
    const float* Wk = (const float*)d_in[2];
    const float* Wv = (const float*)d_in[3];
    const float* Wo = (const float*)d_in[4];
    float* out = (float*)d_out;

    float *gQ, *gK, *gV, *gA;
    cudaGetSymbolAddress((void**)&gQ, g_Q);
    cudaGetSymbolAddress((void**)&gK, g_K);
    cudaGetSymbolAddress((void**)&gV, g_V);
    cudaGetSymbolAddress((void**)&gA, g_A);

    // QKV projections (fused, 192 blocks)
    sgemm_qkv<<<dim3(12, 16), 256>>>(x, Wq, Wk, Wv, gQ, gK, gV);
    // attention (1024 blocks)
    attn_kernel<<<dim3(SEQ / TQ, HEADS), 256>>>(gQ, gK, gV, gA);
    // output projection
    sgemm128<<<dim3(DIMC / 128, SEQ / 128), 256>>>(gA, Wo, out, SEQ, DIMC, DIMC);
}

// round 2
// speedup vs baseline: 1.9390x; 1.9390x over previous
#include <cuda_runtime.h>
#include <cuda_bf16.h>
#include <math.h>

// ---------------- problem constants ----------------
#define SEQ   2048
#define DIMC  1024
#define HEADS 16
#define KVH   4
#define HD    64
#define KVDIM 256
#define WIN   64
#define NGLOB 32
#define TQ    32
#define SCALE 0.125f

// ---------------- scratch ----------------
__device__ float g_Q[SEQ * DIMC];
__device__ float g_K[SEQ * KVDIM];
__device__ float g_V[SEQ * KVDIM];
__device__ float g_A[SEQ * DIMC];

// ---------------- tf32 helpers ----------------
__device__ __forceinline__ unsigned f2tf32(float f) {
    unsigned r;
    asm("cvt.rna.tf32.f32 %0, %1;" : "=r"(r) : "f"(f));
    return r;
}

__device__ __forceinline__ void mma_tf32(float* c, const unsigned* a, const unsigned* b) {
    asm volatile(
        "mma.sync.aligned.m16n8k8.row.col.f32.tf32.tf32.f32 "
        "{%0,%1,%2,%3}, {%4,%5,%6,%7}, {%8,%9}, {%0,%1,%2,%3};"
        : "+f"(c[0]), "+f"(c[1]), "+f"(c[2]), "+f"(c[3])
        : "r"(a[0]), "r"(a[1]), "r"(a[2]), "r"(a[3]), "r"(b[0]), "r"(b[1]));
}

// smem strides (u32 units), chosen for conflict-free fragment loads
#define AS_STRIDE 20    // BK=16 + 4 pad : 20*grp mod 32 hits all banks
#define BS_STRIDE 136   // BN=128 + 8 pad: 136 mod 32 = 8 -> 8*ctg+grp all banks

// =================================================================
// Core tf32 MMA tile body. Computes the 128x128 tile (by,bx) of
// C[M,N] = A[M,K] @ B[K,N] (row-major). K divisible by 16.
// 256 threads. B pointed at its own column window; ldb/ldc = row strides.
// =================================================================
__device__ __forceinline__ void tf32_tile(
    const float* __restrict__ A, const float* __restrict__ B,
    float* __restrict__ C, int K, int ldb, int ldc,
    int by, unsigned* As, unsigned* Bs)
{
    const int tid  = threadIdx.x;
    const int lane = tid & 31, warp = tid >> 5;
    const int wm = (warp >> 2) * 64;      // warp m offset (0/64)
    const int wn = (warp & 3) * 32;       // warp n offset (0..96)
    const int grp = lane >> 2, ctg = lane & 3;

    float acc[4][4][4];
#pragma unroll
    for (int i = 0; i < 4; i++)
#pragma unroll
        for (int j = 0; j < 4; j++)
#pragma unroll
            for (int r = 0; r < 4; r++) acc[i][j][r] = 0.f;

    // gmem->smem mapping
    const int ar = tid >> 2, ac = (tid & 3) * 4;      // A: rows 0..63 (+64), col groups
    const int br = tid >> 6, bc = (tid & 63) * 2;     // B: rows 0..3 (+4,+8,+12), 2 cols

    const float* Aptr = A + (size_t)(by * 128 + ar) * K + ac;

    for (int k0 = 0; k0 < K; k0 += 16) {
#pragma unroll
        for (int half = 0; half < 2; half++) {
            float4 av = *(const float4*)(Aptr + (size_t)(half * 64) * K + k0);
            unsigned* dst = &As[(ar + half * 64) * AS_STRIDE + ac];
            dst[0] = f2tf32(av.x); dst[1] = f2tf32(av.y);
            dst[2] = f2tf32(av.z); dst[3] = f2tf32(av.w);
        }
#pragma unroll
        for (int half = 0; half < 4; half++) {
            const float* bp = B + (size_t)(k0 + br + half * 4) * ldb + bc;
            unsigned* dst = &Bs[(br + half * 4) * BS_STRIDE + bc];
            float2 bv = *(const float2*)bp;
            dst[0] = f2tf32(bv.x); dst[1] = f2tf32(bv.y);
        }
        __syncthreads();

#pragma unroll
        for (int ks = 0; ks < 2; ks++) {
            const int kk = ks * 8;
            unsigned a[4][4], b[4][2];
#pragma unroll
            for (int mi = 0; mi < 4; mi++) {
                const unsigned* p = &As[(wm + mi * 16 + grp) * AS_STRIDE + kk + ctg];
                a[mi][0] = p[0];
                a[mi][1] = p[8 * AS_STRIDE];
                a[mi][2] = p[4];
                a[mi][3] = p[8 * AS_STRIDE + 4];
            }
#pragma unroll
            for (int ni = 0; ni < 4; ni++) {
                const unsigned* p = &Bs[(kk + ctg) * BS_STRIDE + wn + ni * 8 + grp];
                b[ni][0] = p[0];
                b[ni][1] = p[4 * BS_STRIDE];
            }
#pragma unroll
            for (int mi = 0; mi < 4; mi++)
#pragma unroll
                for (int ni = 0; ni < 4; ni++)
                    mma_tf32(acc[mi][ni], a[mi], b[ni]);
        }
        __syncthreads();
    }

    // epilogue
#pragma unroll
    for (int mi = 0; mi < 4; mi++) {
        const int row = by * 128 + wm + mi * 16 + grp;
#pragma unroll
        for (int ni = 0; ni < 4; ni++) {
            const int col = wn + ni * 8 + 2 * ctg;
            *(float2*)(C + (size_t)row * ldc + col) =
                make_float2(acc[mi][ni][0], acc[mi][ni][1]);
            *(float2*)(C + (size_t)(row + 8) * ldc + col) =
                make_float2(acc[mi][ni][2], acc[mi][ni][3]);
        }
    }
}

// ---------------- generic GEMM (for Wo) ----------------
__global__ __launch_bounds__(256, 2)
void tf32_gemm(const float* __restrict__ A, const float* __restrict__ B,
               float* __restrict__ C, int K, int N)
{
    __shared__ unsigned As[128 * AS_STRIDE];
    __shared__ unsigned Bs[16 * BS_STRIDE];
    tf32_tile(A, B + blockIdx.x * 128, C + blockIdx.x * 128,
              K, N, N, blockIdx.y, As, Bs);
}

// ---------------- fused QKV GEMM ----------------
__global__ __launch_bounds__(256, 2)
void tf32_qkv(const float* __restrict__ A,
              const float* __restrict__ Wq, const float* __restrict__ Wk,
              const float* __restrict__ Wv,
              float* __restrict__ Q, float* __restrict__ Ko, float* __restrict__ Vo)
{
    __shared__ unsigned As[128 * AS_STRIDE];
    __shared__ unsigned Bs[16 * BS_STRIDE];

    const int bx = blockIdx.x;
    const float* B; float* C; int Nb; int bcol0;
    if (bx < 8)       { B = Wq; C = Q;  Nb = DIMC;  bcol0 = bx * 128; }
    else if (bx < 10) { B = Wk; C = Ko; Nb = KVDIM; bcol0 = (bx - 8) * 128; }
    else              { B = Wv; C = Vo; Nb = KVDIM; bcol0 = (bx - 10) * 128; }

    tf32_tile(A, B + bcol0, C + bcol0, DIMC, Nb, Nb, blockIdx.y, As, Bs);
}

// =================================================================
// Attention (unchanged from R1)
// =================================================================
__global__ __launch_bounds__(256)
void attn_kernel(const float* __restrict__ Q, const float* __restrict__ K,
                 const float* __restrict__ V, float* __restrict__ O)
{
    __shared__ float Qs[TQ][HD];
    __shared__ float Ks[TQ + WIN][HD + 1];
    __shared__ float Sl[TQ][WIN + 1];
    __shared__ float Sg[TQ][NGLOB];

    const int h    = blockIdx.y;
    const int kvh  = h >> 2;
    const int q0   = blockIdx.x * TQ;
    const int tid  = threadIdx.x;
    const float slope = exp2f(-0.5f * (float)(h + 1));

    for (int i = tid; i < TQ * HD; i += 256) {
        int q = i >> 6, d = i & 63;
        Qs[q][d] = Q[(size_t)(q0 + q) * DIMC + h * HD + d];
    }
    for (int i = tid; i < (TQ + WIN) * HD; i += 256) {
        int r = i >> 6, d = i & 63;
        int key = q0 - WIN + r;
        Ks[r][d] = (key >= 0) ? K[(size_t)key * KVDIM + kvh * HD + d] : 0.f;
    }
    for (int i = tid; i < NGLOB * HD; i += 256) {
        int g = i >> 6, d = i & 63;
        Sl[g][d] = K[(size_t)(g * WIN) * KVDIM + kvh * HD + d];
    }
    __syncthreads();

    for (int it = tid; it < TQ * NGLOB; it += 256) {
        int q = it >> 5, g = it & 31;
        float s = 0.f;
#pragma unroll
        for (int d = 0; d < HD; d++) s = fmaf(Qs[q][d], Sl[g][d], s);
        Sg[q][g] = s * SCALE;
    }
    __syncthreads();

    for (int it = tid; it < TQ * (WIN + 1); it += 256) {
        int q = it / (WIN + 1);
        int j = it - q * (WIN + 1);
        int key = q0 + q - WIN + j;
        float s = -3.0e38f;
        if (key >= 0) {
            float acc = 0.f;
#pragma unroll
            for (int d = 0; d < HD; d++) acc = fmaf(Qs[q][d], Ks[q + j][d], acc);
            s = acc * SCALE + (float)(j - WIN) * slope;
        }
        Sl[q][j] = s;
    }
    __syncthreads();

    {
        const int warp = tid >> 5, lane = tid & 31;
        for (int q = warp * 4; q < warp * 4 + 4; q++) {
            float m = -3.0e38f;
            for (int j = lane; j < WIN + 1; j += 32) m = fmaxf(m, Sl[q][j]);
#pragma unroll
            for (int o = 16; o; o >>= 1) m = fmaxf(m, __shfl_xor_sync(~0u, m, o));
            float sum = 0.f;
            for (int j = lane; j < WIN + 1; j += 32) {
                float e = __expf(Sl[q][j] - m);
                Sl[q][j] = e;
                sum += e;
            }
#pragma unroll
            for (int o = 16; o; o >>= 1) sum += __shfl_xor_sync(~0u, sum, o);
            float inv = 1.f / sum;
            for (int j = lane; j < WIN + 1; j += 32) Sl[q][j] *= inv;
            float gv = Sg[q][lane];
            float mg = gv;
#pragma unroll
            for (int o = 16; o; o >>= 1) mg = fmaxf(mg, __shfl_xor_sync(~0u, mg, o));
            float e = __expf(gv - mg);
            float sg = e;
#pragma unroll
            for (int o = 16; o; o >>= 1) sg += __shfl_xor_sync(~0u, sg, o);
            Sg[q][lane] = e / sg;
        }
    }
    __syncthreads();

    for (int i = tid; i < (TQ + WIN) * HD; i += 256) {
        int r = i >> 6, d = i & 63;
        int key = q0 - WIN + r;
        Ks[r][d] = (key >= 0) ? V[(size_t)key * KVDIM + kvh * HD + d] : 0.f;
    }
    for (int i = tid; i < NGLOB * HD; i += 256) {
        int g = i >> 6, d = i & 63;
        Qs[g][d] = V[(size_t)(g * WIN) * KVDIM + kvh * HD + d];
    }
    __syncthreads();

    for (int it = tid; it < TQ * HD; it += 256) {
        int q = it >> 6, d = it & 63;
        float acc = 0.f;
#pragma unroll
        for (int j = 0; j < WIN + 1; j++) acc = fmaf(Sl[q][j], Ks[q + j][d], acc);
#pragma unroll
        for (int g = 0; g < NGLOB; g++) acc = fmaf(Sg[q][g], Qs[g][d], acc);
        O[(size_t)(q0 + q) * DIMC + h * HD + d] = acc;
    }
}

// =================================================================
extern "C" void kernel_launch(void* const* d_in, const int* in_sizes, int n_in,
                              void* d_out, int out_size)
{
    const float* x  = (const float*)d_in[0];
    const float* Wq = (const float*)d_in[1];
    const float* Wk = (const float*)d_in[2];
    const float* Wv = (const float*)d_in[3];
    const float* Wo = (const float*)d_in[4];
    float* out = (float*)d_out;

    float *gQ, *gK, *gV, *gA;
    cudaGetSymbolAddress((void**)&gQ, g_Q);
    cudaGetSymbolAddress((void**)&gK, g_K);
    cudaGetSymbolAddress((void**)&gV, g_V);
    cudaGetSymbolAddress((void**)&gA, g_A);

    tf32_qkv<<<dim3(12, 16), 256>>>(x, Wq, Wk, Wv, gQ, gK, gV);
    attn_kernel<<<dim3(SEQ / TQ, HEADS), 256>>>(gQ, gK, gV, gA);
    tf32_gemm<<<dim3(DIMC / 128, SEQ / 128), 256>>>(gA, Wo, out, DIMC, DIMC);
}

// round 7
// speedup vs baseline: 2.1023x; 1.0842x over previous
#include <cuda_runtime.h>
#include <cuda_bf16.h>
#include <math.h>

// ---------------- problem constants ----------------
#define SEQ   2048
#define DIMC  1024
#define HEADS 16
#define KVH   4
#define HD    64
#define KVDIM 256
#define WIN   64
#define NGLOB 32
#define TQ    32
#define SCALE 0.125f

// ---------------- scratch ----------------
__device__ float g_Q[SEQ * DIMC];
__device__ float g_K[SEQ * KVDIM];
__device__ float g_V[SEQ * KVDIM];
__device__ float g_A[SEQ * DIMC];
// tf32-valued copies of inputs
__device__ float g_Xc [SEQ * DIMC];
__device__ float g_Wqc[DIMC * DIMC];
__device__ float g_Wkc[DIMC * KVDIM];
__device__ float g_Wvc[DIMC * KVDIM];
__device__ float g_Woc[DIMC * DIMC];

// ---------------- helpers ----------------
__device__ __forceinline__ unsigned f2tf32(float f) {
    unsigned r;
    asm("cvt.rna.tf32.f32 %0, %1;" : "=r"(r) : "f"(f));
    return r;
}
__device__ __forceinline__ float tf32r(float f) { return __uint_as_float(f2tf32(f)); }

__device__ __forceinline__ void mma_tf32(float* c, const unsigned* a, const unsigned* b) {
    asm volatile(
        "mma.sync.aligned.m16n8k8.row.col.f32.tf32.tf32.f32 "
        "{%0,%1,%2,%3}, {%4,%5,%6,%7}, {%8,%9}, {%0,%1,%2,%3};"
        : "+f"(c[0]), "+f"(c[1]), "+f"(c[2]), "+f"(c[3])
        : "r"(a[0]), "r"(a[1]), "r"(a[2]), "r"(a[3]), "r"(b[0]), "r"(b[1]));
}

__device__ __forceinline__ void cp16(float* dst, const float* src) {
    unsigned s = (unsigned)__cvta_generic_to_shared(dst);
    asm volatile("cp.async.cg.shared.global [%0], [%1], 16;" :: "r"(s), "l"(src));
}
#define CP_COMMIT() asm volatile("cp.async.commit_group;")
#define CP_WAIT1()  asm volatile("cp.async.wait_group 1;")

#define AS_STRIDE 20    // BK=16 + 4 pad  (conflict-free A frags)
#define BS_STRIDE 136   // BN=128 + 8 pad (conflict-free B frags)
#define AS_SZ (128 * AS_STRIDE)
#define BS_SZ (16 * BS_STRIDE)

// =================================================================
// Preconvert fp32 -> tf32-valued fp32 for x and all weights.
// float4 index space, ranges: X 524288 | Wq 262144 | Wk 65536 | Wv 65536 | Wo 262144
// =================================================================
__global__ __launch_bounds__(256)
void cvt_all(const float4* __restrict__ x,  const float4* __restrict__ wq,
             const float4* __restrict__ wk, const float4* __restrict__ wv,
             const float4* __restrict__ wo,
             float4* __restrict__ xc,  float4* __restrict__ wqc,
             float4* __restrict__ wkc, float4* __restrict__ wvc,
             float4* __restrict__ woc)
{
    int i = blockIdx.x * 256 + threadIdx.x;
    const float4* src; float4* dst; int off;
    if      (i <  524288) { src = x;  dst = xc;  off = 0;      }
    else if (i <  786432) { src = wq; dst = wqc; off = 524288; }
    else if (i <  851968) { src = wk; dst = wkc; off = 786432; }
    else if (i <  917504) { src = wv; dst = wvc; off = 851968; }
    else                  { src = wo; dst = woc; off = 917504; }
    int j = i - off;
    float4 v = src[j];
    v.x = tf32r(v.x); v.y = tf32r(v.y); v.z = tf32r(v.z); v.w = tf32r(v.w);
    dst[j] = v;
}

// =================================================================
// tf32 MMA tile with cp.async 2-stage pipeline.
// 128x128 tile of C[M,N]=A@B, row-major, K%16==0. Inputs tf32-valued fp32.
// =================================================================
__device__ __forceinline__ void tf32_tile_pipe(
    const float* __restrict__ A, const float* __restrict__ B,
    float* __restrict__ C, int K, int ldb, int ldc,
    int by, float* As, float* Bs)   // As: 2*AS_SZ, Bs: 2*BS_SZ
{
    const int tid  = threadIdx.x;
    const int lane = tid & 31, warp = tid >> 5;
    const int wm = (warp >> 2) * 64;
    const int wn = (warp & 3) * 32;
    const int grp = lane >> 2, ctg = lane & 3;

    float acc[4][4][4];
#pragma unroll
    for (int i = 0; i < 4; i++)
#pragma unroll
        for (int j = 0; j < 4; j++)
#pragma unroll
            for (int r = 0; r < 4; r++) acc[i][j][r] = 0.f;

    // gmem->smem async copy mapping
    const int arow = tid >> 1,  acg = (tid & 1)  * 8;   // 128 rows x 16 cols
    const int brow = tid >> 4,  bcg = (tid & 15) * 8;   // 16 rows x 128 cols
    const float* Aptr = A + (size_t)(by * 128 + arow) * K + acg;
    const float* Bptr = B + (size_t)brow * ldb + bcg;

    const int NC = K / 16;

    // prefetch chunk 0 -> stage 0
    {
        float* ad = As + arow * AS_STRIDE + acg;
        cp16(ad, Aptr); cp16(ad + 4, Aptr + 4);
        float* bd = Bs + brow * BS_STRIDE + bcg;
        cp16(bd, Bptr); cp16(bd + 4, Bptr + 4);
    }
    CP_COMMIT();

    for (int c = 0; c < NC; c++) {
        const int cur = c & 1;
        if (c + 1 < NC) {
            const int k0 = (c + 1) * 16;
            float* ad = As + (cur ^ 1) * AS_SZ + arow * AS_STRIDE + acg;
            cp16(ad, Aptr + k0); cp16(ad + 4, Aptr + k0 + 4);
            float* bd = Bs + (cur ^ 1) * BS_SZ + brow * BS_STRIDE + bcg;
            const float* bp = Bptr + (size_t)k0 * ldb;
            cp16(bd, bp); cp16(bd + 4, bp + 4);
        }
        CP_COMMIT();
        CP_WAIT1();
        __syncthreads();

        const float* as = As + cur * AS_SZ;
        const float* bs = Bs + cur * BS_SZ;
#pragma unroll
        for (int ks = 0; ks < 2; ks++) {
            const int kk = ks * 8;
            unsigned a[4][4], b[4][2];
#pragma unroll
            for (int mi = 0; mi < 4; mi++) {
                const float* p = &as[(wm + mi * 16 + grp) * AS_STRIDE + kk + ctg];
                a[mi][0] = __float_as_uint(p[0]);
                a[mi][1] = __float_as_uint(p[8 * AS_STRIDE]);
                a[mi][2] = __float_as_uint(p[4]);
                a[mi][3] = __float_as_uint(p[8 * AS_STRIDE + 4]);
            }
#pragma unroll
            for (int ni = 0; ni < 4; ni++) {
                const float* p = &bs[(kk + ctg) * BS_STRIDE + wn + ni * 8 + grp];
                b[ni][0] = __float_as_uint(p[0]);
                b[ni][1] = __float_as_uint(p[4 * BS_STRIDE]);
            }
#pragma unroll
            for (int mi = 0; mi < 4; mi++)
#pragma unroll
                for (int ni = 0; ni < 4; ni++)
                    mma_tf32(acc[mi][ni], a[mi], b[ni]);
        }
        __syncthreads();
    }

#pragma unroll
    for (int mi = 0; mi < 4; mi++) {
        const int row = by * 128 + wm + mi * 16 + grp;
#pragma unroll
        for (int ni = 0; ni < 4; ni++) {
            const int col = wn + ni * 8 + 2 * ctg;
            *(float2*)(C + (size_t)row * ldc + col) =
                make_float2(acc[mi][ni][0], acc[mi][ni][1]);
            *(float2*)(C + (size_t)(row + 8) * ldc + col) =
                make_float2(acc[mi][ni][2], acc[mi][ni][3]);
        }
    }
}

__global__ __launch_bounds__(256, 2)
void tf32_gemm(const float* __restrict__ A, const float* __restrict__ B,
               float* __restrict__ C, int K, int N)
{
    __shared__ float As[2 * AS_SZ];
    __shared__ float Bs[2 * BS_SZ];
    tf32_tile_pipe(A, B + blockIdx.x * 128, C + blockIdx.x * 128,
                   K, N, N, blockIdx.y, As, Bs);
}

__global__ __launch_bounds__(256, 2)
void tf32_qkv(const float* __restrict__ A,
              const float* __restrict__ Wq, const float* __restrict__ Wk,
              const float* __restrict__ Wv,
              float* __restrict__ Q, float* __restrict__ Ko, float* __restrict__ Vo)
{
    __shared__ float As[2 * AS_SZ];
    __shared__ float Bs[2 * BS_SZ];

    const int bx = blockIdx.x;
    const float* B; float* C; int Nb; int bcol0;
    if (bx < 8)       { B = Wq; C = Q;  Nb = DIMC;  bcol0 = bx * 128; }
    else if (bx < 10) { B = Wk; C = Ko; Nb = KVDIM; bcol0 = (bx - 8) * 128; }
    else              { B = Wv; C = Vo; Nb = KVDIM; bcol0 = (bx - 10) * 128; }

    tf32_tile_pipe(A, B + bcol0, C + bcol0, DIMC, Nb, Nb, blockIdx.y, As, Bs);
}

// =================================================================
// Attention: float4-vectorized smem; K-row stride 68 (16B aligned, conflict-free).
// Output written tf32-rounded so the Wo GEMM can consume raw bits.
// =================================================================
#define KSTR 68

__global__ __launch_bounds__(256)
void attn_kernel(const float* __restrict__ Q, const float* __restrict__ K,
                 const float* __restrict__ V, float* __restrict__ O)
{
    __shared__ float Qs[TQ][HD];            // Q tile; reused as global-V
    __shared__ float Ks[TQ + WIN][KSTR];    // local K; reused as local-V
    __shared__ float Sl[TQ][KSTR];          // global-K staging, then local probs
    __shared__ float Sg[TQ][NGLOB];         // global probs

    const int h    = blockIdx.y;
    const int kvh  = h >> 2;
    const int q0   = blockIdx.x * TQ;
    const int tid  = threadIdx.x;
    const float slope = exp2f(-0.5f * (float)(h + 1));
    const float4 z4 = make_float4(0.f, 0.f, 0.f, 0.f);

    // ---- stage Q, local K, global K ----
    for (int i = tid; i < TQ * 16; i += 256) {
        int q = i >> 4, d4 = i & 15;
        *(float4*)&Qs[q][d4 * 4] =
            *(const float4*)&Q[(size_t)(q0 + q) * DIMC + h * HD + d4 * 4];
    }
    for (int i = tid; i < (TQ + WIN) * 16; i += 256) {
        int r = i >> 4, d4 = i & 15;
        int key = q0 - WIN + r;
        *(float4*)&Ks[r][d4 * 4] = (key >= 0)
            ? *(const float4*)&K[(size_t)key * KVDIM + kvh * HD + d4 * 4] : z4;
    }
    for (int i = tid; i < NGLOB * 16; i += 256) {
        int g = i >> 4, d4 = i & 15;
        *(float4*)&Sl[g][d4 * 4] =
            *(const float4*)&K[(size_t)(g * WIN) * KVDIM + kvh * HD + d4 * 4];
    }
    __syncthreads();

    // ---- global scores ----
    for (int it = tid; it < TQ * NGLOB; it += 256) {
        int q = it >> 5, g = it & 31;
        float s = 0.f;
#pragma unroll
        for (int d4 = 0; d4 < 16; d4++) {
            float4 qv = *(const float4*)&Qs[q][d4 * 4];
            float4 kv = *(const float4*)&Sl[g][d4 * 4];
            s = fmaf(qv.x, kv.x, s); s = fmaf(qv.y, kv.y, s);
            s = fmaf(qv.z, kv.z, s); s = fmaf(qv.w, kv.w, s);
        }
        Sg[q][g] = s * SCALE;
    }
    __syncthreads();   // done reading Sl as K-global before overwrite

    // ---- local scores ----
    for (int it = tid; it < TQ * (WIN + 1); it += 256) {
        int q = it / (WIN + 1);
        int j = it - q * (WIN + 1);
        int key = q0 + q - WIN + j;
        float s = -3.0e38f;
        if (key >= 0) {
            float acc = 0.f;
#pragma unroll
            for (int d4 = 0; d4 < 16; d4++) {
                float4 qv = *(const float4*)&Qs[q][d4 * 4];
                float4 kv = *(const float4*)&Ks[q + j][d4 * 4];
                acc = fmaf(qv.x, kv.x, acc); acc = fmaf(qv.y, kv.y, acc);
                acc = fmaf(qv.z, kv.z, acc); acc = fmaf(qv.w, kv.w, acc);
            }
            s = acc * SCALE + (float)(j - WIN) * slope;
        }
        Sl[q][j] = s;
    }
    __syncthreads();

    // ---- softmaxes ----
    {
        const int warp = tid >> 5, lane = tid & 31;
        for (int q = warp * 4; q < warp * 4 + 4; q++) {
            float m = -3.0e38f;
            for (int j = lane; j < WIN + 1; j += 32) m = fmaxf(m, Sl[q][j]);
#pragma unroll
            for (int o = 16; o; o >>= 1) m = fmaxf(m, __shfl_xor_sync(~0u, m, o));
            float sum = 0.f;
            for (int j = lane; j < WIN + 1; j += 32) {
                float e = __expf(Sl[q][j] - m);
                Sl[q][j] = e;
                sum += e;
            }
#pragma unroll
            for (int o = 16; o; o >>= 1) sum += __shfl_xor_sync(~0u, sum, o);
            float inv = 1.f / sum;
            for (int j = lane; j < WIN + 1; j += 32) Sl[q][j] *= inv;

            float gv = Sg[q][lane];
            float mg = gv;
#pragma unroll
            for (int o = 16; o; o >>= 1) mg = fmaxf(mg, __shfl_xor_sync(~0u, mg, o));
            float e = __expf(gv - mg);
            float sg = e;
#pragma unroll
            for (int o = 16; o; o >>= 1) sg += __shfl_xor_sync(~0u, sg, o);
            Sg[q][lane] = e / sg;
        }
    }
    __syncthreads();

    // ---- reload V (local into Ks, global into Qs) ----
    for (int i = tid; i < (TQ + WIN) * 16; i += 256) {
        int r = i >> 4, d4 = i & 15;
        int key = q0 - WIN + r;
        *(float4*)&Ks[r][d4 * 4] = (key >= 0)
            ? *(const float4*)&V[(size_t)key * KVDIM + kvh * HD + d4 * 4] : z4;
    }
    for (int i = tid; i < NGLOB * 16; i += 256) {
        int g = i >> 4, d4 = i & 15;
        *(float4*)&Qs[g][d4 * 4] =
            *(const float4*)&V[(size_t)(g * WIN) * KVDIM + kvh * HD + d4 * 4];
    }
    __syncthreads();

    // ---- PV (vectorized), store tf32-rounded ----
    for (int it = tid; it < TQ * 16; it += 256) {
        int q = it >> 4, d4 = it & 15;
        float4 acc = z4;
#pragma unroll 13
        for (int j = 0; j < WIN + 1; j++) {
            float p = Sl[q][j];
            float4 vv = *(const float4*)&Ks[q + j][d4 * 4];
            acc.x = fmaf(p, vv.x, acc.x); acc.y = fmaf(p, vv.y, acc.y);
            acc.z = fmaf(p, vv.z, acc.z); acc.w = fmaf(p, vv.w, acc.w);
        }
#pragma unroll
        for (int g = 0; g < NGLOB; g++) {
            float p = Sg[q][g];
            float4 vv = *(const float4*)&Qs[g][d4 * 4];
            acc.x = fmaf(p, vv.x, acc.x); acc.y = fmaf(p, vv.y, acc.y);
            acc.z = fmaf(p, vv.z, acc.z); acc.w = fmaf(p, vv.w, acc.w);
        }
        float4 r;
        r.x = tf32r(acc.x); r.y = tf32r(acc.y);
        r.z = tf32r(acc.z); r.w = tf32r(acc.w);
        *(float4*)&O[(size_t)(q0 + q) * DIMC + h * HD + d4 * 4] = r;
    }
}

// =================================================================
extern "C" void kernel_launch(void* const* d_in, const int* in_sizes, int n_in,
                              void* d_out, int out_size)
{
    const float* x  = (const float*)d_in[0];
    const float* Wq = (const float*)d_in[1];
    const float* Wk = (const float*)d_in[2];
    const float* Wv = (const float*)d_in[3];
    const float* Wo = (const float*)d_in[4];
    float* out = (float*)d_out;

    float *gQ, *gK, *gV, *gA, *gXc, *gWqc, *gWkc, *gWvc, *gWoc;
    cudaGetSymbolAddress((void**)&gQ,  g_Q);
    cudaGetSymbolAddress((void**)&gK,  g_K);
    cudaGetSymbolAddress((void**)&gV,  g_V);
    cudaGetSymbolAddress((void**)&gA,  g_A);
    cudaGetSymbolAddress((void**)&gXc, g_Xc);
    cudaGetSymbolAddress((void**)&gWqc, g_Wqc);
    cudaGetSymbolAddress((void**)&gWkc, g_Wkc);
    cudaGetSymbolAddress((void**)&gWvc, g_Wvc);
    cudaGetSymbolAddress((void**)&gWoc, g_Woc);

    cvt_all<<<4608, 256>>>((const float4*)x, (const float4*)Wq, (const float4*)Wk,
                           (const float4*)Wv, (const float4*)Wo,
                           (float4*)gXc, (float4*)gWqc, (float4*)gWkc,
                           (float4*)gWvc, (float4*)gWoc);
    tf32_qkv<<<dim3(12, 16), 256>>>(gXc, gWqc, gWkc, gWvc, gQ, gK, gV);
    attn_kernel<<<dim3(SEQ / TQ, HEADS), 256>>>(gQ, gK, gV, gA);
    tf32_gemm<<<dim3(DIMC / 128, SEQ / 128), 256>>>(gA, gWoc, out, DIMC, DIMC);
}

// round 9
// speedup vs baseline: 2.4359x; 1.1587x over previous
#include <cuda_runtime.h>
#include <cuda_bf16.h>
#include <math.h>

// ---------------- problem constants ----------------
#define SEQ   2048
#define DIMC  1024
#define HEADS 16
#define KVH   4
#define HD    64
#define KVDIM 256
#define WIN   64
#define NGLOB 32
#define TQ    32
#define SCALE 0.125f

// ---------------- scratch ----------------
__device__ float g_Q[SEQ * DIMC];
__device__ float g_K[SEQ * KVDIM];
__device__ float g_V[SEQ * KVDIM];
__device__ float g_A[SEQ * DIMC];
__device__ float g_Xc [SEQ * DIMC];
__device__ float g_Wqc[DIMC * DIMC];
__device__ float g_Wkc[DIMC * KVDIM];
__device__ float g_Wvc[DIMC * KVDIM];
__device__ float g_Woc[DIMC * DIMC];

// ---------------- helpers ----------------
__device__ __forceinline__ unsigned f2tf32(float f) {
    unsigned r; asm("cvt.rna.tf32.f32 %0, %1;" : "=r"(r) : "f"(f)); return r;
}
__device__ __forceinline__ float tf32r(float f) { return __uint_as_float(f2tf32(f)); }

__device__ __forceinline__ void mma_tf32(float* c, const unsigned* a, const unsigned* b) {
    asm volatile(
        "mma.sync.aligned.m16n8k8.row.col.f32.tf32.tf32.f32 "
        "{%0,%1,%2,%3}, {%4,%5,%6,%7}, {%8,%9}, {%0,%1,%2,%3};"
        : "+f"(c[0]), "+f"(c[1]), "+f"(c[2]), "+f"(c[3])
        : "r"(a[0]), "r"(a[1]), "r"(a[2]), "r"(a[3]), "r"(b[0]), "r"(b[1]));
}

__device__ __forceinline__ void cp16(float* dst, const float* src) {
    unsigned s = (unsigned)__cvta_generic_to_shared(dst);
    asm volatile("cp.async.cg.shared.global [%0], [%1], 16;" :: "r"(s), "l"(src));
}
__device__ __forceinline__ void cp16z(float* dst, const float* src, bool valid) {
    unsigned s = (unsigned)__cvta_generic_to_shared(dst);
    int sz = valid ? 16 : 0;
    asm volatile("cp.async.cg.shared.global [%0], [%1], 16, %2;"
                 :: "r"(s), "l"(src), "r"(sz));
}
#define CP_COMMIT() asm volatile("cp.async.commit_group;")
#define CP_WAIT1()  asm volatile("cp.async.wait_group 1;")
#define CP_WAIT0()  asm volatile("cp.async.wait_group 0;")

// ---------------- GEMM geometry ----------------
#define BM 128
#define BN 64
#define BK 32
#define ASTR 36              // BK + 4 pad (conflict-free A frags: (36g+c)%32=4g+c)
#define BSTR 68              // BN + 4 pad (conflict-free B frags: (68c+g)%32=4c+g)
#define ASZ (BM * ASTR)      // 4608 floats
#define BSZ (BK * BSTR)      // 2176 floats
#define GSTAGE (ASZ + BSZ)   // 6784 floats
#define GEMM_SMEM (2 * GSTAGE * 4)   // 54272 bytes
#define NCHUNK (DIMC / BK)   // 32

// =================================================================
// Preconvert fp32 -> tf32-valued fp32 (x + all 4 weights), float4 space.
// =================================================================
__global__ __launch_bounds__(256)
void cvt_all(const float4* __restrict__ x,  const float4* __restrict__ wq,
             const float4* __restrict__ wk, const float4* __restrict__ wv,
             const float4* __restrict__ wo,
             float4* __restrict__ xc,  float4* __restrict__ wqc,
             float4* __restrict__ wkc, float4* __restrict__ wvc,
             float4* __restrict__ woc)
{
    int i = blockIdx.x * 256 + threadIdx.x;
    const float4* src; float4* dst; int off;
    if      (i <  524288) { src = x;  dst = xc;  off = 0;      }
    else if (i <  786432) { src = wq; dst = wqc; off = 524288; }
    else if (i <  851968) { src = wk; dst = wkc; off = 786432; }
    else if (i <  917504) { src = wv; dst = wvc; off = 851968; }
    else                  { src = wo; dst = woc; off = 917504; }
    int j = i - off;
    float4 v = src[j];
    v.x = tf32r(v.x); v.y = tf32r(v.y); v.z = tf32r(v.z); v.w = tf32r(v.w);
    dst[j] = v;
}

// =================================================================
// 128x64 tf32 warp-MMA tile, 2-stage cp.async, 256 threads.
// A base (lda = DIMC = 1024), B pre-offset to column base (row stride ldb),
// C pre-offset to column base (row stride ldc). by = M-tile index.
// =================================================================
__device__ __forceinline__ void mma_tile(const float* __restrict__ A,
                                         const float* __restrict__ B,
                                         float* __restrict__ C,
                                         int ldb, int ldc, int by, float* sm)
{
    const int tid  = threadIdx.x;
    const int lane = tid & 31, warp = tid >> 5;
    const int wm = (warp >> 1) * 32;     // 4 warps in M
    const int wn = (warp & 1) * 32;      // 2 warps in N
    const int grp = lane >> 2, ctg = lane & 3;

    float acc[2][4][4];
#pragma unroll
    for (int i = 0; i < 2; i++)
#pragma unroll
        for (int j = 0; j < 4; j++)
#pragma unroll
            for (int r = 0; r < 4; r++) acc[i][j][r] = 0.f;

    // cp.async mappings
    // A: 128 rows x 8 float4-groups -> 1024 slots, 4 per thread
    // B: 32 k-rows x 16 float4-groups -> 512 slots, 2 per thread
    const float* Abase = A + (size_t)(by * BM) * DIMC;

    auto load_chunk = [&](int c, int s) {
        float* as = sm + s * GSTAGE;
        float* bs = as + ASZ;
        const int k0 = c * BK;
#pragma unroll
        for (int i = 0; i < 4; i++) {
            int idx = tid + i * 256;
            int r = idx >> 3, g = idx & 7;
            cp16(as + r * ASTR + g * 4, Abase + (size_t)r * DIMC + k0 + g * 4);
        }
#pragma unroll
        for (int i = 0; i < 2; i++) {
            int idx = tid + i * 256;
            int r = idx >> 4, g = idx & 15;
            cp16(bs + r * BSTR + g * 4, B + (size_t)(k0 + r) * ldb + g * 4);
        }
    };

    load_chunk(0, 0);
    CP_COMMIT();

#pragma unroll 1
    for (int c = 0; c < NCHUNK; c++) {
        const int s = c & 1;
        if (c + 1 < NCHUNK) load_chunk(c + 1, s ^ 1);
        CP_COMMIT();
        CP_WAIT1();
        __syncthreads();

        const float* as = sm + s * GSTAGE;
        const float* bs = as + ASZ;
#pragma unroll
        for (int ks = 0; ks < 4; ks++) {
            const int kk = ks * 8;
            unsigned a[2][4], b[4][2];
#pragma unroll
            for (int mi = 0; mi < 2; mi++) {
                const float* p = &as[(wm + mi * 16 + grp) * ASTR + kk + ctg];
                a[mi][0] = __float_as_uint(p[0]);
                a[mi][1] = __float_as_uint(p[8 * ASTR]);
                a[mi][2] = __float_as_uint(p[4]);
                a[mi][3] = __float_as_uint(p[8 * ASTR + 4]);
            }
#pragma unroll
            for (int ni = 0; ni < 4; ni++) {
                const float* p = &bs[(kk + ctg) * BSTR + wn + ni * 8 + grp];
                b[ni][0] = __float_as_uint(p[0]);
                b[ni][1] = __float_as_uint(p[4 * BSTR]);
            }
#pragma unroll
            for (int mi = 0; mi < 2; mi++)
#pragma unroll
                for (int ni = 0; ni < 4; ni++)
                    mma_tf32(acc[mi][ni], a[mi], b[ni]);
        }
        __syncthreads();
    }

#pragma unroll
    for (int mi = 0; mi < 2; mi++) {
        const int row = by * BM + wm + mi * 16 + grp;
#pragma unroll
        for (int ni = 0; ni < 4; ni++) {
            const int col = wn + ni * 8 + 2 * ctg;
            *(float2*)(C + (size_t)row * ldc + col) =
                make_float2(acc[mi][ni][0], acc[mi][ni][1]);
            *(float2*)(C + (size_t)(row + 8) * ldc + col) =
                make_float2(acc[mi][ni][2], acc[mi][ni][3]);
        }
    }
}

// ---- fused QKV: logical N = 1536 -> 24 col tiles of 64. grid (24,16) ----
__global__ __launch_bounds__(256, 2)
void tf32_qkv(const float* __restrict__ Xc,
              const float* __restrict__ Wq, const float* __restrict__ Wk,
              const float* __restrict__ Wv,
              float* __restrict__ Q, float* __restrict__ Ko, float* __restrict__ Vo)
{
    extern __shared__ float sm[];
    const int bx = blockIdx.x;
    const float* B; float* C; int ld;
    if (bx < 16)      { B = Wq + bx * 64;        C = Q  + bx * 64;        ld = DIMC;  }
    else if (bx < 20) { B = Wk + (bx - 16) * 64; C = Ko + (bx - 16) * 64; ld = KVDIM; }
    else              { B = Wv + (bx - 20) * 64; C = Vo + (bx - 20) * 64; ld = KVDIM; }
    mma_tile(Xc, B, C, ld, ld, blockIdx.y, sm);
}

// ---- Wo GEMM: grid (16,16) ----
__global__ __launch_bounds__(256, 2)
void tf32_wo(const float* __restrict__ Ac, const float* __restrict__ Wo,
             float* __restrict__ Out)
{
    extern __shared__ float sm[];
    mma_tile(Ac, Wo + blockIdx.x * 64, Out + blockIdx.x * 64,
             DIMC, DIMC, blockIdx.y, sm);
}

// =================================================================
// Attention: cp.async staged Q/K (group 1) + V prefetch (group 2).
// Dynamic smem 81920 B. Grid (64,16), 256 threads.
// =================================================================
#define KSTR 68

__global__ __launch_bounds__(256)
void attn_kernel(const float* __restrict__ Q, const float* __restrict__ K,
                 const float* __restrict__ V, float* __restrict__ O)
{
    extern __shared__ float sm[];
    float (*Qs)[HD]   = (float(*)[HD])  sm;              // 2048
    float (*Ks)[KSTR] = (float(*)[KSTR])(sm + 2048);     // 6528
    float (*Vl)[KSTR] = (float(*)[KSTR])(sm + 8576);     // 6528
    float (*Vg)[KSTR] = (float(*)[KSTR])(sm + 15104);    // 2176
    float (*Sl)[KSTR] = (float(*)[KSTR])(sm + 17280);    // 2176 (Kg staging, then probs)
    float (*Sg)[NGLOB]= (float(*)[NGLOB])(sm + 19456);   // 1024

    const int h    = blockIdx.y;
    const int kvh  = h >> 2;
    const int q0   = blockIdx.x * TQ;
    const int tid  = threadIdx.x;
    const float slope = exp2f(-0.5f * (float)(h + 1));
    const float4 z4 = make_float4(0.f, 0.f, 0.f, 0.f);

    // ---- group 1: Q tile, local K, global K (into Sl) ----
    for (int i = tid; i < TQ * 16; i += 256) {
        int q = i >> 4, d4 = i & 15;
        cp16(&Qs[q][d4 * 4], &Q[(size_t)(q0 + q) * DIMC + h * HD + d4 * 4]);
    }
    for (int i = tid; i < (TQ + WIN) * 16; i += 256) {
        int r = i >> 4, d4 = i & 15;
        int key = q0 - WIN + r;
        cp16z(&Ks[r][d4 * 4], &K[(size_t)max(key, 0) * KVDIM + kvh * HD + d4 * 4],
              key >= 0);
    }
    for (int i = tid; i < NGLOB * 16; i += 256) {
        int g = i >> 4, d4 = i & 15;
        cp16(&Sl[g][d4 * 4], &K[(size_t)(g * WIN) * KVDIM + kvh * HD + d4 * 4]);
    }
    CP_COMMIT();

    // ---- group 2: local V, global V (arrive during score/softmax) ----
    for (int i = tid; i < (TQ + WIN) * 16; i += 256) {
        int r = i >> 4, d4 = i & 15;
        int key = q0 - WIN + r;
        cp16z(&Vl[r][d4 * 4], &V[(size_t)max(key, 0) * KVDIM + kvh * HD + d4 * 4],
              key >= 0);
    }
    for (int i = tid; i < NGLOB * 16; i += 256) {
        int g = i >> 4, d4 = i & 15;
        cp16(&Vg[g][d4 * 4], &V[(size_t)(g * WIN) * KVDIM + kvh * HD + d4 * 4]);
    }
    CP_COMMIT();
    CP_WAIT1();          // Q/K ready; V still in flight
    __syncthreads();

    // ---- global scores (Sl holds Kg) ----
    for (int it = tid; it < TQ * NGLOB; it += 256) {
        int q = it >> 5, g = it & 31;
        float s = 0.f;
#pragma unroll
        for (int d4 = 0; d4 < 16; d4++) {
            float4 qv = *(const float4*)&Qs[q][d4 * 4];
            float4 kv = *(const float4*)&Sl[g][d4 * 4];
            s = fmaf(qv.x, kv.x, s); s = fmaf(qv.y, kv.y, s);
            s = fmaf(qv.z, kv.z, s); s = fmaf(qv.w, kv.w, s);
        }
        Sg[q][g] = s * SCALE;
    }
    __syncthreads();

    // ---- local scores (overwrite Sl) ----
    for (int it = tid; it < TQ * (WIN + 1); it += 256) {
        int q = it / (WIN + 1);
        int j = it - q * (WIN + 1);
        int key = q0 + q - WIN + j;
        float s = -3.0e38f;
        if (key >= 0) {
            float acc = 0.f;
#pragma unroll
            for (int d4 = 0; d4 < 16; d4++) {
                float4 qv = *(const float4*)&Qs[q][d4 * 4];
                float4 kv = *(const float4*)&Ks[q + j][d4 * 4];
                acc = fmaf(qv.x, kv.x, acc); acc = fmaf(qv.y, kv.y, acc);
                acc = fmaf(qv.z, kv.z, acc); acc = fmaf(qv.w, kv.w, acc);
            }
            s = acc * SCALE + (float)(j - WIN) * slope;
        }
        Sl[q][j] = s;
    }
    __syncthreads();

    // ---- softmaxes ----
    {
        const int warp = tid >> 5, lane = tid & 31;
        for (int q = warp * 4; q < warp * 4 + 4; q++) {
            float m = -3.0e38f;
            for (int j = lane; j < WIN + 1; j += 32) m = fmaxf(m, Sl[q][j]);
#pragma unroll
            for (int o = 16; o; o >>= 1) m = fmaxf(m, __shfl_xor_sync(~0u, m, o));
            float sum = 0.f;
            for (int j = lane; j < WIN + 1; j += 32) {
                float e = __expf(Sl[q][j] - m);
                Sl[q][j] = e;
                sum += e;
            }
#pragma unroll
            for (int o = 16; o; o >>= 1) sum += __shfl_xor_sync(~0u, sum, o);
            float inv = 1.f / sum;
            for (int j = lane; j < WIN + 1; j += 32) Sl[q][j] *= inv;

            float gv = Sg[q][lane];
            float mg = gv;
#pragma unroll
            for (int o = 16; o; o >>= 1) mg = fmaxf(mg, __shfl_xor_sync(~0u, mg, o));
            float e = __expf(gv - mg);
            float sg = e;
#pragma unroll
            for (int o = 16; o; o >>= 1) sg += __shfl_xor_sync(~0u, sg, o);
            Sg[q][lane] = e / sg;
        }
    }
    CP_WAIT0();          // V resident
    __syncthreads();

    // ---- PV, store tf32-rounded ----
    for (int it = tid; it < TQ * 16; it += 256) {
        int q = it >> 4, d4 = it & 15;
        float4 acc = z4;
#pragma unroll 13
        for (int j = 0; j < WIN + 1; j++) {
            float p = Sl[q][j];
            float4 vv = *(const float4*)&Vl[q + j][d4 * 4];
            acc.x = fmaf(p, vv.x, acc.x); acc.y = fmaf(p, vv.y, acc.y);
            acc.z = fmaf(p, vv.z, acc.z); acc.w = fmaf(p, vv.w, acc.w);
        }
#pragma unroll
        for (int g = 0; g < NGLOB; g++) {
            float p = Sg[q][g];
            float4 vv = *(const float4*)&Vg[g][d4 * 4];
            acc.x = fmaf(p, vv.x, acc.x); acc.y = fmaf(p, vv.y, acc.y);
            acc.z = fmaf(p, vv.z, acc.z); acc.w = fmaf(p, vv.w, acc.w);
        }
        float4 r;
        r.x = tf32r(acc.x); r.y = tf32r(acc.y);
        r.z = tf32r(acc.z); r.w = tf32r(acc.w);
        *(float4*)&O[(size_t)(q0 + q) * DIMC + h * HD + d4 * 4] = r;
    }
}

#define ATTN_SMEM (20480 * 4)

// =================================================================
extern "C" void kernel_launch(void* const* d_in, const int* in_sizes, int n_in,
                              void* d_out, int out_size)
{
    const float* x  = (const float*)d_in[0];
    const float* Wq = (const float*)d_in[1];
    const float* Wk = (const float*)d_in[2];
    const float* Wv = (const float*)d_in[3];
    const float* Wo = (const float*)d_in[4];
    float* out = (float*)d_out;

    float *gQ, *gK, *gV, *gA, *gXc, *gWqc, *gWkc, *gWvc, *gWoc;
    cudaGetSymbolAddress((void**)&gQ,  g_Q);
    cudaGetSymbolAddress((void**)&gK,  g_K);
    cudaGetSymbolAddress((void**)&gV,  g_V);
    cudaGetSymbolAddress((void**)&gA,  g_A);
    cudaGetSymbolAddress((void**)&gXc, g_Xc);
    cudaGetSymbolAddress((void**)&gWqc, g_Wqc);
    cudaGetSymbolAddress((void**)&gWkc, g_Wkc);
    cudaGetSymbolAddress((void**)&gWvc, g_Wvc);
    cudaGetSymbolAddress((void**)&gWoc, g_Woc);

    cudaFuncSetAttribute(tf32_qkv,   cudaFuncAttributeMaxDynamicSharedMemorySize, GEMM_SMEM);
    cudaFuncSetAttribute(tf32_wo,    cudaFuncAttributeMaxDynamicSharedMemorySize, GEMM_SMEM);
    cudaFuncSetAttribute(attn_kernel, cudaFuncAttributeMaxDynamicSharedMemorySize, ATTN_SMEM);

    cvt_all<<<4608, 256>>>((const float4*)x, (const float4*)Wq, (const float4*)Wk,
                           (const float4*)Wv, (const float4*)Wo,
                           (float4*)gXc, (float4*)gWqc, (float4*)gWkc,
                           (float4*)gWvc, (float4*)gWoc);
    tf32_qkv<<<dim3(24, 16), 256, GEMM_SMEM>>>(gXc, gWqc, gWkc, gWvc, gQ, gK, gV);
    attn_kernel<<<dim3(SEQ / TQ, HEADS), 256, ATTN_SMEM>>>(gQ, gK, gV, gA);
    tf32_wo<<<dim3(16, 16), 256, GEMM_SMEM>>>(gA, gWoc, out);
}

// round 10
// speedup vs baseline: 2.6708x; 1.0964x over previous
#include <cuda_runtime.h>
#include <cuda_bf16.h>
#include <math.h>

// ---------------- problem constants ----------------
#define SEQ   2048
#define DIMC  1024
#define HEADS 16
#define KVH   4
#define HD    64
#define KVDIM 256
#define WIN   64
#define NGLOB 32
#define TQ    32
#define SCALE 0.125f

// ---------------- scratch ----------------
__device__ float g_Q[SEQ * DIMC];
__device__ float g_K[SEQ * KVDIM];
__device__ float g_V[SEQ * KVDIM];
__device__ float g_A[SEQ * DIMC];
__device__ float g_Xc [SEQ * DIMC];        // tf32-rounded x
__device__ float g_WqT[DIMC * DIMC];       // transposed tf32 weights [N][K]
__device__ float g_WkT[KVDIM * DIMC];
__device__ float g_WvT[KVDIM * DIMC];
__device__ float g_WoT[DIMC * DIMC];

// ---------------- helpers ----------------
__device__ __forceinline__ unsigned f2tf32(float f) {
    unsigned r; asm("cvt.rna.tf32.f32 %0, %1;" : "=r"(r) : "f"(f)); return r;
}
__device__ __forceinline__ float tf32r(float f) { return __uint_as_float(f2tf32(f)); }

__device__ __forceinline__ void mma_tf32(float* c, const unsigned* a, const unsigned* b) {
    asm volatile(
        "mma.sync.aligned.m16n8k8.row.col.f32.tf32.tf32.f32 "
        "{%0,%1,%2,%3}, {%4,%5,%6,%7}, {%8,%9}, {%0,%1,%2,%3};"
        : "+f"(c[0]), "+f"(c[1]), "+f"(c[2]), "+f"(c[3])
        : "r"(a[0]), "r"(a[1]), "r"(a[2]), "r"(a[3]), "r"(b[0]), "r"(b[1]));
}

__device__ __forceinline__ void ldsm4(unsigned* r, unsigned saddr) {
    asm volatile("ldmatrix.sync.aligned.m8n8.x4.shared.b16 {%0,%1,%2,%3}, [%4];"
                 : "=r"(r[0]), "=r"(r[1]), "=r"(r[2]), "=r"(r[3]) : "r"(saddr));
}

__device__ __forceinline__ void cp16(float* dst, const float* src) {
    unsigned s = (unsigned)__cvta_generic_to_shared(dst);
    asm volatile("cp.async.cg.shared.global [%0], [%1], 16;" :: "r"(s), "l"(src));
}
__device__ __forceinline__ void cp16z(float* dst, const float* src, bool valid) {
    unsigned s = (unsigned)__cvta_generic_to_shared(dst);
    int sz = valid ? 16 : 0;
    asm volatile("cp.async.cg.shared.global [%0], [%1], 16, %2;"
                 :: "r"(s), "l"(src), "r"(sz));
}
#define CP_COMMIT() asm volatile("cp.async.commit_group;")
#define CP_WAIT1()  asm volatile("cp.async.wait_group 1;")
#define CP_WAIT0()  asm volatile("cp.async.wait_group 0;")

__device__ __forceinline__ unsigned smem_u32(const void* p) {
    return (unsigned)__cvta_generic_to_shared(p);
}

// ---------------- GEMM geometry ----------------
#define BM 128
#define BN 64
#define BK 32
#define RSTR 36                    // row stride in floats (144B): conflict-free
#define A_FL (BM * RSTR)           // 4608 floats
#define B_FL (BN * RSTR)           // 2304 floats
#define ST_FL (A_FL + B_FL)        // 6912 floats
#define ST_BYTES (ST_FL * 4)       // 27648 B
#define GEMM_SMEM (3 * ST_BYTES)   // 82944 B (3 stages)
#define NCH (DIMC / BK)            // 32

// =================================================================
// Convert: blocks 0..2047 -> x elementwise tf32-round (float4);
// blocks 2048..4607 -> 32x32 transpose tiles of the 4 weights (tf32-rounded),
// producing WT[n][k] with row stride DIMC.
// =================================================================
__global__ __launch_bounds__(256)
void cvt_all(const float4* __restrict__ x, const float* __restrict__ wq,
             const float* __restrict__ wk, const float* __restrict__ wv,
             const float* __restrict__ wo,
             float4* __restrict__ xc, float* __restrict__ wqT,
             float* __restrict__ wkT, float* __restrict__ wvT,
             float* __restrict__ woT)
{
    __shared__ float s[32][33];
    const int tid = threadIdx.x;
    if (blockIdx.x < 2048) {
        int i = blockIdx.x * 256 + tid;
        float4 v = x[i];
        v.x = tf32r(v.x); v.y = tf32r(v.y); v.z = tf32r(v.z); v.w = tf32r(v.w);
        xc[i] = v;
        return;
    }
    int b = blockIdx.x - 2048;
    const float* W; float* WT; int N;
    if (b < 1024)       { W = wq; WT = wqT; N = DIMC; }
    else if (b < 1280)  { b -= 1024; W = wk; WT = wkT; N = KVDIM; }
    else if (b < 1536)  { b -= 1280; W = wv; WT = wvT; N = KVDIM; }
    else                { b -= 1536; W = wo; WT = woT; N = DIMC; }
    const int ntile = N / 32;
    const int n0 = (b % ntile) * 32;
    const int k0 = (b / ntile) * 32;
    const int c = tid & 31, r0 = tid >> 5;
#pragma unroll
    for (int rr = 0; rr < 4; rr++) {
        int r = r0 + rr * 8;
        s[r][c] = tf32r(W[(size_t)(k0 + r) * N + n0 + c]);
    }
    __syncthreads();
#pragma unroll
    for (int rr = 0; rr < 4; rr++) {
        int r = r0 + rr * 8;
        WT[(size_t)(n0 + r) * DIMC + k0 + c] = s[c][r];
    }
}

// =================================================================
// 128x64 tf32 MMA tile: ldmatrix fragment feeds, 3-stage cp.async,
// one __syncthreads per chunk. 256 threads.
// A: row-major [*, DIMC]; BT: [N][K] pre-offset to col0 row; C pre-offset.
// =================================================================
__device__ __forceinline__ void mma_tile(const float* __restrict__ A,
                                         const float* __restrict__ BT,
                                         float* __restrict__ C,
                                         int ldc, int by, float* sm)
{
    const int tid  = threadIdx.x;
    const int lane = tid & 31, warp = tid >> 5;
    const int wm = (warp >> 1) * 32;     // 4 warps in M
    const int wn = (warp & 1) * 32;      // 2 warps in N
    const int grp = lane >> 2, ctg = lane & 3;

    float acc[2][4][4];
#pragma unroll
    for (int i = 0; i < 2; i++)
#pragma unroll
        for (int j = 0; j < 4; j++)
#pragma unroll
            for (int r = 0; r < 4; r++) acc[i][j][r] = 0.f;

    const float* Abase = A + (size_t)(by * BM) * DIMC;

    // cp.async mappings: A 128r x 8 groups (4/thread); B 64n x 8 groups (2/thread)
    auto load_chunk = [&](int c, int s) {
        float* as = sm + s * ST_FL;
        float* bs = as + A_FL;
        const int k0 = c * BK;
#pragma unroll
        for (int i = 0; i < 4; i++) {
            int idx = tid + i * 256;
            int r = idx >> 3, g = idx & 7;
            cp16(as + r * RSTR + g * 4, Abase + (size_t)r * DIMC + k0 + g * 4);
        }
#pragma unroll
        for (int i = 0; i < 2; i++) {
            int idx = tid + i * 256;
            int n = idx >> 3, g = idx & 7;
            cp16(bs + n * RSTR + g * 4, BT + (size_t)n * DIMC + k0 + g * 4);
        }
    };

    // ldmatrix lane-address offsets (bytes within a stage)
    const unsigned aOff = (unsigned)(((wm + (lane & 15)) * RSTR + (lane >> 4) * 4) * 4);
    const unsigned bOff = (unsigned)(A_FL * 4 +
        ((wn + ((lane >> 4) << 3) + (lane & 7)) * RSTR + ((lane >> 3) & 1) * 4) * 4);
    const unsigned sb = smem_u32(sm);

    load_chunk(0, 0); CP_COMMIT();
    load_chunk(1, 1); CP_COMMIT();

#pragma unroll 2
    for (int c = 0; c < NCH; c++) {
        CP_WAIT1();
        __syncthreads();
        const int s = c % 3;
        if (c + 2 < NCH) load_chunk(c + 2, (c + 2) % 3);
        CP_COMMIT();

        const unsigned stb = sb + (unsigned)(s * ST_BYTES);
        const unsigned aA = stb + aOff;
        const unsigned bA = stb + bOff;
#pragma unroll
        for (int ks = 0; ks < 4; ks++) {
            unsigned a0[4], a1[4], b0[4], b1[4];
            ldsm4(a0, aA + ks * 32);                 // mi=0
            ldsm4(a1, aA + 2304 + ks * 32);          // mi=1 (+16 rows * 144B)
            ldsm4(b0, bA + ks * 32);                 // ni={0,1}
            ldsm4(b1, bA + 2304 + ks * 32);          // ni={2,3} (+16 cols * 144B)
            mma_tf32(acc[0][0], a0, &b0[0]);
            mma_tf32(acc[0][1], a0, &b0[2]);
            mma_tf32(acc[0][2], a0, &b1[0]);
            mma_tf32(acc[0][3], a0, &b1[2]);
            mma_tf32(acc[1][0], a1, &b0[0]);
            mma_tf32(acc[1][1], a1, &b0[2]);
            mma_tf32(acc[1][2], a1, &b1[0]);
            mma_tf32(acc[1][3], a1, &b1[2]);
        }
    }

#pragma unroll
    for (int mi = 0; mi < 2; mi++) {
        const int row = by * BM + wm + mi * 16 + grp;
#pragma unroll
        for (int ni = 0; ni < 4; ni++) {
            const int col = wn + ni * 8 + 2 * ctg;
            *(float2*)(C + (size_t)row * ldc + col) =
                make_float2(acc[mi][ni][0], acc[mi][ni][1]);
            *(float2*)(C + (size_t)(row + 8) * ldc + col) =
                make_float2(acc[mi][ni][2], acc[mi][ni][3]);
        }
    }
}

// ---- fused QKV: 24 col tiles of 64 (16 Q + 4 K + 4 V). grid (24,16) ----
__global__ __launch_bounds__(256, 2)
void tf32_qkv(const float* __restrict__ Xc,
              const float* __restrict__ WqT, const float* __restrict__ WkT,
              const float* __restrict__ WvT,
              float* __restrict__ Q, float* __restrict__ Ko, float* __restrict__ Vo)
{
    extern __shared__ float sm[];
    const int bx = blockIdx.x;
    const float* BT; float* C; int ld;
    if (bx < 16)      { BT = WqT + (size_t)bx * 64 * DIMC;        C = Q  + bx * 64;        ld = DIMC;  }
    else if (bx < 20) { BT = WkT + (size_t)(bx - 16) * 64 * DIMC; C = Ko + (bx - 16) * 64; ld = KVDIM; }
    else              { BT = WvT + (size_t)(bx - 20) * 64 * DIMC; C = Vo + (bx - 20) * 64; ld = KVDIM; }
    mma_tile(Xc, BT, C, ld, blockIdx.y, sm);
}

// ---- Wo GEMM: grid (16,16) ----
__global__ __launch_bounds__(256, 2)
void tf32_wo(const float* __restrict__ Ac, const float* __restrict__ WoT,
             float* __restrict__ Out)
{
    extern __shared__ float sm[];
    mma_tile(Ac, WoT + (size_t)blockIdx.x * 64 * DIMC, Out + blockIdx.x * 64,
             DIMC, blockIdx.y, sm);
}

// =================================================================
// Attention (unchanged from R9): cp.async staged Q/K + V prefetch.
// =================================================================
#define KSTR 68

__global__ __launch_bounds__(256)
void attn_kernel(const float* __restrict__ Q, const float* __restrict__ K,
                 const float* __restrict__ V, float* __restrict__ O)
{
    extern __shared__ float sm[];
    float (*Qs)[HD]   = (float(*)[HD])  sm;
    float (*Ks)[KSTR] = (float(*)[KSTR])(sm + 2048);
    float (*Vl)[KSTR] = (float(*)[KSTR])(sm + 8576);
    float (*Vg)[KSTR] = (float(*)[KSTR])(sm + 15104);
    float (*Sl)[KSTR] = (float(*)[KSTR])(sm + 17280);
    float (*Sg)[NGLOB]= (float(*)[NGLOB])(sm + 19456);

    const int h    = blockIdx.y;
    const int kvh  = h >> 2;
    const int q0   = blockIdx.x * TQ;
    const int tid  = threadIdx.x;
    const float slope = exp2f(-0.5f * (float)(h + 1));
    const float4 z4 = make_float4(0.f, 0.f, 0.f, 0.f);

    for (int i = tid; i < TQ * 16; i += 256) {
        int q = i >> 4, d4 = i & 15;
        cp16(&Qs[q][d4 * 4], &Q[(size_t)(q0 + q) * DIMC + h * HD + d4 * 4]);
    }
    for (int i = tid; i < (TQ + WIN) * 16; i += 256) {
        int r = i >> 4, d4 = i & 15;
        int key = q0 - WIN + r;
        cp16z(&Ks[r][d4 * 4], &K[(size_t)max(key, 0) * KVDIM + kvh * HD + d4 * 4],
              key >= 0);
    }
    for (int i = tid; i < NGLOB * 16; i += 256) {
        int g = i >> 4, d4 = i & 15;
        cp16(&Sl[g][d4 * 4], &K[(size_t)(g * WIN) * KVDIM + kvh * HD + d4 * 4]);
    }
    CP_COMMIT();

    for (int i = tid; i < (TQ + WIN) * 16; i += 256) {
        int r = i >> 4, d4 = i & 15;
        int key = q0 - WIN + r;
        cp16z(&Vl[r][d4 * 4], &V[(size_t)max(key, 0) * KVDIM + kvh * HD + d4 * 4],
              key >= 0);
    }
    for (int i = tid; i < NGLOB * 16; i += 256) {
        int g = i >> 4, d4 = i & 15;
        cp16(&Vg[g][d4 * 4], &V[(size_t)(g * WIN) * KVDIM + kvh * HD + d4 * 4]);
    }
    CP_COMMIT();
    CP_WAIT1();
    __syncthreads();

    for (int it = tid; it < TQ * NGLOB; it += 256) {
        int q = it >> 5, g = it & 31;
        float s = 0.f;
#pragma unroll
        for (int d4 = 0; d4 < 16; d4++) {
            float4 qv = *(const float4*)&Qs[q][d4 * 4];
            float4 kv = *(const float4*)&Sl[g][d4 * 4];
            s = fmaf(qv.x, kv.x, s); s = fmaf(qv.y, kv.y, s);
            s = fmaf(qv.z, kv.z, s); s = fmaf(qv.w, kv.w, s);
        }
        Sg[q][g] = s * SCALE;
    }
    __syncthreads();

    for (int it = tid; it < TQ * (WIN + 1); it += 256) {
        int q = it / (WIN + 1);
        int j = it - q * (WIN + 1);
        int key = q0 + q - WIN + j;
        float s = -3.0e38f;
        if (key >= 0) {
            float acc = 0.f;
#pragma unroll
            for (int d4 = 0; d4 < 16; d4++) {
                float4 qv = *(const float4*)&Qs[q][d4 * 4];
                float4 kv = *(const float4*)&Ks[q + j][d4 * 4];
                acc = fmaf(qv.x, kv.x, acc); acc = fmaf(qv.y, kv.y, acc);
                acc = fmaf(qv.z, kv.z, acc); acc = fmaf(qv.w, kv.w, acc);
            }
            s = acc * SCALE + (float)(j - WIN) * slope;
        }
        Sl[q][j] = s;
    }
    __syncthreads();

    {
        const int warp = tid >> 5, lane = tid & 31;
        for (int q = warp * 4; q < warp * 4 + 4; q++) {
            float m = -3.0e38f;
            for (int j = lane; j < WIN + 1; j += 32) m = fmaxf(m, Sl[q][j]);
#pragma unroll
            for (int o = 16; o; o >>= 1) m = fmaxf(m, __shfl_xor_sync(~0u, m, o));
            float sum = 0.f;
            for (int j = lane; j < WIN + 1; j += 32) {
                float e = __expf(Sl[q][j] - m);
                Sl[q][j] = e;
                sum += e;
            }
#pragma unroll
            for (int o = 16; o; o >>= 1) sum += __shfl_xor_sync(~0u, sum, o);
            float inv = 1.f / sum;
            for (int j = lane; j < WIN + 1; j += 32) Sl[q][j] *= inv;

            float gv = Sg[q][lane];
            float mg = gv;
#pragma unroll
            for (int o = 16; o; o >>= 1) mg = fmaxf(mg, __shfl_xor_sync(~0u, mg, o));
            float e = __expf(gv - mg);
            float sg = e;
#pragma unroll
            for (int o = 16; o; o >>= 1) sg += __shfl_xor_sync(~0u, sg, o);
            Sg[q][lane] = e / sg;
        }
    }
    CP_WAIT0();
    __syncthreads();

    for (int it = tid; it < TQ * 16; it += 256) {
        int q = it >> 4, d4 = it & 15;
        float4 acc = z4;
#pragma unroll 13
        for (int j = 0; j < WIN + 1; j++) {
            float p = Sl[q][j];
            float4 vv = *(const float4*)&Vl[q + j][d4 * 4];
            acc.x = fmaf(p, vv.x, acc.x); acc.y = fmaf(p, vv.y, acc.y);
            acc.z = fmaf(p, vv.z, acc.z); acc.w = fmaf(p, vv.w, acc.w);
        }
#pragma unroll
        for (int g = 0; g < NGLOB; g++) {
            float p = Sg[q][g];
            float4 vv = *(const float4*)&Vg[g][d4 * 4];
            acc.x = fmaf(p, vv.x, acc.x); acc.y = fmaf(p, vv.y, acc.y);
            acc.z = fmaf(p, vv.z, acc.z); acc.w = fmaf(p, vv.w, acc.w);
        }
        float4 r;
        r.x = tf32r(acc.x); r.y = tf32r(acc.y);
        r.z = tf32r(acc.z); r.w = tf32r(acc.w);
        *(float4*)&O[(size_t)(q0 + q) * DIMC + h * HD + d4 * 4] = r;
    }
}

#define ATTN_SMEM (20480 * 4)

// =================================================================
extern "C" void kernel_launch(void* const* d_in, const int* in_sizes, int n_in,
                              void* d_out, int out_size)
{
    const float* x  = (const float*)d_in[0];
    const float* Wq = (const float*)d_in[1];
    const float* Wk = (const float*)d_in[2];
    const float* Wv = (const float*)d_in[3];
    const float* Wo = (const float*)d_in[4];
    float* out = (float*)d_out;

    float *gQ, *gK, *gV, *gA, *gXc, *gWqT, *gWkT, *gWvT, *gWoT;
    cudaGetSymbolAddress((void**)&gQ,  g_Q);
    cudaGetSymbolAddress((void**)&gK,  g_K);
    cudaGetSymbolAddress((void**)&gV,  g_V);
    cudaGetSymbolAddress((void**)&gA,  g_A);
    cudaGetSymbolAddress((void**)&gXc, g_Xc);
    cudaGetSymbolAddress((void**)&gWqT, g_WqT);
    cudaGetSymbolAddress((void**)&gWkT, g_WkT);
    cudaGetSymbolAddress((void**)&gWvT, g_WvT);
    cudaGetSymbolAddress((void**)&gWoT, g_WoT);

    cudaFuncSetAttribute(tf32_qkv,   cudaFuncAttributeMaxDynamicSharedMemorySize, GEMM_SMEM);
    cudaFuncSetAttribute(tf32_wo,    cudaFuncAttributeMaxDynamicSharedMemorySize, GEMM_SMEM);
    cudaFuncSetAttribute(attn_kernel, cudaFuncAttributeMaxDynamicSharedMemorySize, ATTN_SMEM);

    cvt_all<<<4608, 256>>>((const float4*)x, Wq, Wk, Wv, Wo,
                           (float4*)gXc, gWqT, gWkT, gWvT, gWoT);
    tf32_qkv<<<dim3(24, 16), 256, GEMM_SMEM>>>(gXc, gWqT, gWkT, gWvT, gQ, gK, gV);
    attn_kernel<<<dim3(SEQ / TQ, HEADS), 256, ATTN_SMEM>>>(gQ, gK, gV, gA);
    tf32_wo<<<dim3(16, 16), 256, GEMM_SMEM>>>(gA, gWoT, out);
}

// round 11
// speedup vs baseline: 3.1924x; 1.1953x over previous
#include <cuda_runtime.h>
#include <cuda_bf16.h>
#include <math.h>

// ---------------- problem constants ----------------
#define SEQ   2048
#define DIMC  1024
#define HEADS 16
#define KVH   4
#define HD    64
#define KVDIM 256
#define WIN   64
#define NGLOB 32
#define TQ    32
#define SCALE 0.125f

// ---------------- scratch ----------------
__device__ float g_Q[SEQ * DIMC];
__device__ float g_K[SEQ * KVDIM];
__device__ float g_V[SEQ * KVDIM];
__device__ float g_A[SEQ * DIMC];
__device__ float g_Xc [SEQ * DIMC];        // tf32-rounded x
__device__ float g_WqT[DIMC * DIMC];       // transposed tf32 weights [N][K]
__device__ float g_WkT[KVDIM * DIMC];
__device__ float g_WvT[KVDIM * DIMC];
__device__ float g_WoT[DIMC * DIMC];

// ---------------- helpers ----------------
__device__ __forceinline__ unsigned f2tf32(float f) {
    unsigned r; asm("cvt.rna.tf32.f32 %0, %1;" : "=r"(r) : "f"(f)); return r;
}
__device__ __forceinline__ float tf32r(float f) { return __uint_as_float(f2tf32(f)); }

__device__ __forceinline__ void mma_tf32(float* c, const unsigned* a, const unsigned* b) {
    asm volatile(
        "mma.sync.aligned.m16n8k8.row.col.f32.tf32.tf32.f32 "
        "{%0,%1,%2,%3}, {%4,%5,%6,%7}, {%8,%9}, {%0,%1,%2,%3};"
        : "+f"(c[0]), "+f"(c[1]), "+f"(c[2]), "+f"(c[3])
        : "r"(a[0]), "r"(a[1]), "r"(a[2]), "r"(a[3]), "r"(b[0]), "r"(b[1]));
}

__device__ __forceinline__ void ldsm4(unsigned* r, unsigned saddr) {
    asm volatile("ldmatrix.sync.aligned.m8n8.x4.shared.b16 {%0,%1,%2,%3}, [%4];"
                 : "=r"(r[0]), "=r"(r[1]), "=r"(r[2]), "=r"(r[3]) : "r"(saddr));
}
__device__ __forceinline__ void ldsm2(unsigned* r, unsigned saddr) {
    asm volatile("ldmatrix.sync.aligned.m8n8.x2.shared.b16 {%0,%1}, [%2];"
                 : "=r"(r[0]), "=r"(r[1]) : "r"(saddr));
}

__device__ __forceinline__ void cp16(float* dst, const float* src) {
    unsigned s = (unsigned)__cvta_generic_to_shared(dst);
    asm volatile("cp.async.cg.shared.global [%0], [%1], 16;" :: "r"(s), "l"(src));
}
#define CP_COMMIT() asm volatile("cp.async.commit_group;")
#define CP_WAIT1()  asm volatile("cp.async.wait_group 1;")

__device__ __forceinline__ unsigned smem_u32(const void* p) {
    return (unsigned)__cvta_generic_to_shared(p);
}

// ---------------- GEMM geometry (unchanged from R10) ----------------
#define BM 128
#define BN 64
#define BK 32
#define RSTR 36
#define A_FL (BM * RSTR)
#define B_FL (BN * RSTR)
#define ST_FL (A_FL + B_FL)
#define ST_BYTES (ST_FL * 4)
#define GEMM_SMEM (3 * ST_BYTES)
#define NCH (DIMC / BK)

// =================================================================
// Convert: x elementwise tf32-round; weights -> transposed tf32 [N][K].
// =================================================================
__global__ __launch_bounds__(256)
void cvt_all(const float4* __restrict__ x, const float* __restrict__ wq,
             const float* __restrict__ wk, const float* __restrict__ wv,
             const float* __restrict__ wo,
             float4* __restrict__ xc, float* __restrict__ wqT,
             float* __restrict__ wkT, float* __restrict__ wvT,
             float* __restrict__ woT)
{
    __shared__ float s[32][33];
    const int tid = threadIdx.x;
    if (blockIdx.x < 2048) {
        int i = blockIdx.x * 256 + tid;
        float4 v = x[i];
        v.x = tf32r(v.x); v.y = tf32r(v.y); v.z = tf32r(v.z); v.w = tf32r(v.w);
        xc[i] = v;
        return;
    }
    int b = blockIdx.x - 2048;
    const float* W; float* WT; int N;
    if (b < 1024)       { W = wq; WT = wqT; N = DIMC; }
    else if (b < 1280)  { b -= 1024; W = wk; WT = wkT; N = KVDIM; }
    else if (b < 1536)  { b -= 1280; W = wv; WT = wvT; N = KVDIM; }
    else                { b -= 1536; W = wo; WT = woT; N = DIMC; }
    const int ntile = N / 32;
    const int n0 = (b % ntile) * 32;
    const int k0 = (b / ntile) * 32;
    const int c = tid & 31, r0 = tid >> 5;
#pragma unroll
    for (int rr = 0; rr < 4; rr++) {
        int r = r0 + rr * 8;
        s[r][c] = tf32r(W[(size_t)(k0 + r) * N + n0 + c]);
    }
    __syncthreads();
#pragma unroll
    for (int rr = 0; rr < 4; rr++) {
        int r = r0 + rr * 8;
        WT[(size_t)(n0 + r) * DIMC + k0 + c] = s[c][r];
    }
}

// =================================================================
// 128x64 tf32 MMA tile (unchanged from R10)
// =================================================================
__device__ __forceinline__ void mma_tile(const float* __restrict__ A,
                                         const float* __restrict__ BT,
                                         float* __restrict__ C,
                                         int ldc, int by, float* sm)
{
    const int tid  = threadIdx.x;
    const int lane = tid & 31, warp = tid >> 5;
    const int wm = (warp >> 1) * 32;
    const int wn = (warp & 1) * 32;
    const int grp = lane >> 2, ctg = lane & 3;

    float acc[2][4][4];
#pragma unroll
    for (int i = 0; i < 2; i++)
#pragma unroll
        for (int j = 0; j < 4; j++)
#pragma unroll
            for (int r = 0; r < 4; r++) acc[i][j][r] = 0.f;

    const float* Abase = A + (size_t)(by * BM) * DIMC;

    auto load_chunk = [&](int c, int s) {
        float* as = sm + s * ST_FL;
        float* bs = as + A_FL;
        const int k0 = c * BK;
#pragma unroll
        for (int i = 0; i < 4; i++) {
            int idx = tid + i * 256;
            int r = idx >> 3, g = idx & 7;
            cp16(as + r * RSTR + g * 4, Abase + (size_t)r * DIMC + k0 + g * 4);
        }
#pragma unroll
        for (int i = 0; i < 2; i++) {
            int idx = tid + i * 256;
            int n = idx >> 3, g = idx & 7;
            cp16(bs + n * RSTR + g * 4, BT + (size_t)n * DIMC + k0 + g * 4);
        }
    };

    const unsigned aOff = (unsigned)(((wm + (lane & 15)) * RSTR + (lane >> 4) * 4) * 4);
    const unsigned bOff = (unsigned)(A_FL * 4 +
        ((wn + ((lane >> 4) << 3) + (lane & 7)) * RSTR + ((lane >> 3) & 1) * 4) * 4);
    const unsigned sb = smem_u32(sm);

    load_chunk(0, 0); CP_COMMIT();
    load_chunk(1, 1); CP_COMMIT();

#pragma unroll 2
    for (int c = 0; c < NCH; c++) {
        CP_WAIT1();
        __syncthreads();
        const int s = c % 3;
        if (c + 2 < NCH) load_chunk(c + 2, (c + 2) % 3);
        CP_COMMIT();

        const unsigned stb = sb + (unsigned)(s * ST_BYTES);
        const unsigned aA = stb + aOff;
        const unsigned bA = stb + bOff;
#pragma unroll
        for (int ks = 0; ks < 4; ks++) {
            unsigned a0[4], a1[4], b0[4], b1[4];
            ldsm4(a0, aA + ks * 32);
            ldsm4(a1, aA + 2304 + ks * 32);
            ldsm4(b0, bA + ks * 32);
            ldsm4(b1, bA + 2304 + ks * 32);
            mma_tf32(acc[0][0], a0, &b0[0]);
            mma_tf32(acc[0][1], a0, &b0[2]);
            mma_tf32(acc[0][2], a0, &b1[0]);
            mma_tf32(acc[0][3], a0, &b1[2]);
            mma_tf32(acc[1][0], a1, &b0[0]);
            mma_tf32(acc[1][1], a1, &b0[2]);
            mma_tf32(acc[1][2], a1, &b1[0]);
            mma_tf32(acc[1][3], a1, &b1[2]);
        }
    }

#pragma unroll
    for (int mi = 0; mi < 2; mi++) {
        const int row = by * BM + wm + mi * 16 + grp;
#pragma unroll
        for (int ni = 0; ni < 4; ni++) {
            const int col = wn + ni * 8 + 2 * ctg;
            *(float2*)(C + (size_t)row * ldc + col) =
                make_float2(acc[mi][ni][0], acc[mi][ni][1]);
            *(float2*)(C + (size_t)(row + 8) * ldc + col) =
                make_float2(acc[mi][ni][2], acc[mi][ni][3]);
        }
    }
}

__global__ __launch_bounds__(256, 2)
void tf32_qkv(const float* __restrict__ Xc,
              const float* __restrict__ WqT, const float* __restrict__ WkT,
              const float* __restrict__ WvT,
              float* __restrict__ Q, float* __restrict__ Ko, float* __restrict__ Vo)
{
    extern __shared__ float sm[];
    const int bx = blockIdx.x;
    const float* BT; float* C; int ld;
    if (bx < 16)      { BT = WqT + (size_t)bx * 64 * DIMC;        C = Q  + bx * 64;        ld = DIMC;  }
    else if (bx < 20) { BT = WkT + (size_t)(bx - 16) * 64 * DIMC; C = Ko + (bx - 16) * 64; ld = KVDIM; }
    else              { BT = WvT + (size_t)(bx - 20) * 64 * DIMC; C = Vo + (bx - 20) * 64; ld = KVDIM; }
    mma_tile(Xc, BT, C, ld, blockIdx.y, sm);
}

__global__ __launch_bounds__(256, 2)
void tf32_wo(const float* __restrict__ Ac, const float* __restrict__ WoT,
             float* __restrict__ Out)
{
    extern __shared__ float sm[];
    mma_tile(Ac, WoT + (size_t)blockIdx.x * 64 * DIMC, Out + blockIdx.x * 64,
             DIMC, blockIdx.y, sm);
}

// =================================================================
// Tensorized attention. Grid (64,16), 256 threads, 92KB dyn smem.
// Smem (floats): Qs[32][68] | Kl[96][68] | Kg[32][68] | Vt[64][132] | P[32][132]
// =================================================================
#define AT_QS 0
#define AT_KL 2176
#define AT_KG 8704
#define AT_VT 10880
#define AT_P  19328
#define ATTN_SMEM (23552 * 4)

__global__ __launch_bounds__(256)
void attn_mma(const float* __restrict__ Q, const float* __restrict__ K,
              const float* __restrict__ V, float* __restrict__ O)
{
    extern __shared__ float sm[];
    const int h = blockIdx.y, kvh = h >> 2, q0 = blockIdx.x * TQ;
    const int tid = threadIdx.x, lane = tid & 31, warp = tid >> 5;
    const float slope = exp2f(-0.5f * (float)(h + 1));

    // ---- stage Q (tf32-rounded) ----
    for (int i = tid; i < 32 * 16; i += 256) {
        int q = i >> 4, d4 = i & 15;
        float4 v = *(const float4*)&Q[(size_t)(q0 + q) * DIMC + h * HD + d4 * 4];
        v.x = tf32r(v.x); v.y = tf32r(v.y); v.z = tf32r(v.z); v.w = tf32r(v.w);
        *(float4*)&sm[AT_QS + q * 68 + d4 * 4] = v;
    }
    // ---- stage local K (keys q0-64 .. q0+31; zero for key<0) ----
    for (int i = tid; i < 96 * 16; i += 256) {
        int r = i >> 4, d4 = i & 15;
        int key = q0 - 64 + r;
        float4 v = make_float4(0.f, 0.f, 0.f, 0.f);
        if (key >= 0) {
            v = *(const float4*)&K[(size_t)key * KVDIM + kvh * HD + d4 * 4];
            v.x = tf32r(v.x); v.y = tf32r(v.y); v.z = tf32r(v.z); v.w = tf32r(v.w);
        }
        *(float4*)&sm[AT_KL + r * 68 + d4 * 4] = v;
    }
    // ---- stage global K ----
    for (int i = tid; i < 32 * 16; i += 256) {
        int g = i >> 4, d4 = i & 15;
        float4 v = *(const float4*)&K[(size_t)(g * WIN) * KVDIM + kvh * HD + d4 * 4];
        v.x = tf32r(v.x); v.y = tf32r(v.y); v.z = tf32r(v.z); v.w = tf32r(v.w);
        *(float4*)&sm[AT_KG + g * 68 + d4 * 4] = v;
    }
    // ---- stage V transposed: Vt[d][col], col 0..95 local, 96..127 global ----
    for (int i = tid; i < 128 * 16; i += 256) {
        int col = i >> 4, d4 = i & 15;
        int key; bool valid;
        if (col < 96) { key = q0 - 64 + col; valid = (key >= 0); }
        else          { key = (col - 96) * WIN; valid = true; }
        float4 v = make_float4(0.f, 0.f, 0.f, 0.f);
        if (valid) {
            v = *(const float4*)&V[(size_t)key * KVDIM + kvh * HD + d4 * 4];
            v.x = tf32r(v.x); v.y = tf32r(v.y); v.z = tf32r(v.z); v.w = tf32r(v.w);
        }
        sm[AT_VT + (d4 * 4 + 0) * 132 + col] = v.x;
        sm[AT_VT + (d4 * 4 + 1) * 132 + col] = v.y;
        sm[AT_VT + (d4 * 4 + 2) * 132 + col] = v.z;
        sm[AT_VT + (d4 * 4 + 3) * 132 + col] = v.w;
    }
    __syncthreads();

    const unsigned sb = smem_u32(sm);
    const int m0  = (warp >> 2) * 16;     // 2 warps in M
    const int wnl = (warp & 3) * 24;      // local score cols
    const int wng = (warp & 3) * 8;       // global score cols
    const int ln  = lane & 15;
    const int grp = lane >> 2, ctg = lane & 3;

    // ---- score MMAs: local 32x96, global 32x32, K=64 ----
    {
        const unsigned aQ  = sb + (unsigned)((AT_QS + (m0 + ln) * 68 + (lane >> 4) * 4) * 4);
        const unsigned bKl = sb + (unsigned)((AT_KL + (wnl + ((lane >> 4) << 3) + (lane & 7)) * 68 + ((lane >> 3) & 1) * 4) * 4);
        const unsigned bK2 = sb + (unsigned)((AT_KL + (wnl + 16 + (ln & 7)) * 68 + ((ln >> 3) & 1) * 4) * 4);
        const unsigned bKg = sb + (unsigned)((AT_KG + (wng + (ln & 7)) * 68 + ((ln >> 3) & 1) * 4) * 4);

        float accl[3][4], accg[4];
#pragma unroll
        for (int f = 0; f < 3; f++)
#pragma unroll
            for (int r = 0; r < 4; r++) accl[f][r] = 0.f;
#pragma unroll
        for (int r = 0; r < 4; r++) accg[r] = 0.f;

#pragma unroll
        for (int ks = 0; ks < 8; ks++) {
            unsigned a[4], b01[4], b2[2], bg[2];
            ldsm4(a, aQ + ks * 32);
            ldsm4(b01, bKl + ks * 32);
            ldsm2(b2, bK2 + ks * 32);
            ldsm2(bg, bKg + ks * 32);
            mma_tf32(accl[0], a, &b01[0]);
            mma_tf32(accl[1], a, &b01[2]);
            mma_tf32(accl[2], a, b2);
            mma_tf32(accg, a, bg);
        }
        const int row = m0 + grp;
#pragma unroll
        for (int f = 0; f < 3; f++) {
            int col = wnl + f * 8 + 2 * ctg;
            *(float2*)&sm[AT_P + row * 132 + col]       = make_float2(accl[f][0], accl[f][1]);
            *(float2*)&sm[AT_P + (row + 8) * 132 + col] = make_float2(accl[f][2], accl[f][3]);
        }
        int colg = 96 + wng + 2 * ctg;
        *(float2*)&sm[AT_P + row * 132 + colg]       = make_float2(accg[0], accg[1]);
        *(float2*)&sm[AT_P + (row + 8) * 132 + colg] = make_float2(accg[2], accg[3]);
    }
    __syncthreads();

    // ---- softmaxes (warp per 4 rows), write tf32-rounded probs ----
    for (int q = warp * 4; q < warp * 4 + 4; q++) {
        float l[3]; bool vld[3];
        float m = -3.0e38f;
#pragma unroll
        for (int t = 0; t < 3; t++) {
            int r = lane + t * 32;
            vld[t] = (r >= q) && (r <= q + 64) && (q0 - 64 + r >= 0);
            l[t] = vld[t] ? sm[AT_P + q * 132 + r] * SCALE + (float)(r - q - 64) * slope
                          : -3.0e38f;
            m = fmaxf(m, l[t]);
        }
#pragma unroll
        for (int o = 16; o; o >>= 1) m = fmaxf(m, __shfl_xor_sync(~0u, m, o));
        float e[3], sum = 0.f;
#pragma unroll
        for (int t = 0; t < 3; t++) {
            e[t] = vld[t] ? __expf(l[t] - m) : 0.f;
            sum += e[t];
        }
#pragma unroll
        for (int o = 16; o; o >>= 1) sum += __shfl_xor_sync(~0u, sum, o);
        float inv = 1.f / sum;
#pragma unroll
        for (int t = 0; t < 3; t++)
            sm[AT_P + q * 132 + lane + t * 32] = tf32r(e[t] * inv);

        float gl = sm[AT_P + q * 132 + 96 + lane] * SCALE;
        float mg = gl;
#pragma unroll
        for (int o = 16; o; o >>= 1) mg = fmaxf(mg, __shfl_xor_sync(~0u, mg, o));
        float ge = __expf(gl - mg);
        float gs = ge;
#pragma unroll
        for (int o = 16; o; o >>= 1) gs += __shfl_xor_sync(~0u, gs, o);
        sm[AT_P + q * 132 + 96 + lane] = tf32r(ge / gs);
    }
    __syncthreads();

    // ---- PV: 32x64, K=128 (local||global) ----
    {
        const int n0 = (warp & 3) * 16;
        const unsigned aP = sb + (unsigned)((AT_P + (m0 + ln) * 132 + (lane >> 4) * 4) * 4);
        const unsigned bV = sb + (unsigned)((AT_VT + (n0 + ((lane >> 4) << 3) + (lane & 7)) * 132 + ((lane >> 3) & 1) * 4) * 4);

        float acco[2][4];
#pragma unroll
        for (int f = 0; f < 2; f++)
#pragma unroll
            for (int r = 0; r < 4; r++) acco[f][r] = 0.f;

#pragma unroll
        for (int ks = 0; ks < 16; ks++) {
            unsigned a[4], b[4];
            ldsm4(a, aP + ks * 32);
            ldsm4(b, bV + ks * 32);
            mma_tf32(acco[0], a, &b[0]);
            mma_tf32(acco[1], a, &b[2]);
        }

        const int row = m0 + grp;
#pragma unroll
        for (int f = 0; f < 2; f++) {
            int col = h * HD + n0 + f * 8 + 2 * ctg;
            *(float2*)&O[(size_t)(q0 + row) * DIMC + col] =
                make_float2(tf32r(acco[f][0]), tf32r(acco[f][1]));
            *(float2*)&O[(size_t)(q0 + row + 8) * DIMC + col] =
                make_float2(tf32r(acco[f][2]), tf32r(acco[f][3]));
        }
    }
}

// =================================================================
extern "C" void kernel_launch(void* const* d_in, const int* in_sizes, int n_in,
                              void* d_out, int out_size)
{
    const float* x  = (const float*)d_in[0];
    const float* Wq = (const float*)d_in[1];
    const float* Wk = (const float*)d_in[2];
    const float* Wv = (const float*)d_in[3];
    const float* Wo = (const float*)d_in[4];
    float* out = (float*)d_out;

    float *gQ, *gK, *gV, *gA, *gXc, *gWqT, *gWkT, *gWvT, *gWoT;
    cudaGetSymbolAddress((void**)&gQ,  g_Q);
    cudaGetSymbolAddress((void**)&gK,  g_K);
    cudaGetSymbolAddress((void**)&gV,  g_V);
    cudaGetSymbolAddress((void**)&gA,  g_A);
    cudaGetSymbolAddress((void**)&gXc, g_Xc);
    cudaGetSymbolAddress((void**)&gWqT, g_WqT);
    cudaGetSymbolAddress((void**)&gWkT, g_WkT);
    cudaGetSymbolAddress((void**)&gWvT, g_WvT);
    cudaGetSymbolAddress((void**)&gWoT, g_WoT);

    cudaFuncSetAttribute(tf32_qkv, cudaFuncAttributeMaxDynamicSharedMemorySize, GEMM_SMEM);
    cudaFuncSetAttribute(tf32_wo,  cudaFuncAttributeMaxDynamicSharedMemorySize, GEMM_SMEM);
    cudaFuncSetAttribute(attn_mma, cudaFuncAttributeMaxDynamicSharedMemorySize, ATTN_SMEM);

    cvt_all<<<4608, 256>>>((const float4*)x, Wq, Wk, Wv, Wo,
                           (float4*)gXc, gWqT, gWkT, gWvT, gWoT);
    tf32_qkv<<<dim3(24, 16), 256, GEMM_SMEM>>>(gXc, gWqT, gWkT, gWvT, gQ, gK, gV);
    attn_mma<<<dim3(SEQ / TQ, HEADS), 256, ATTN_SMEM>>>(gQ, gK, gV, gA);
    tf32_wo<<<dim3(16, 16), 256, GEMM_SMEM>>>(gA, gWoT, out);
}

// round 12
// speedup vs baseline: 3.5868x; 1.1235x over previous
#include <cuda_runtime.h>
#include <cuda_bf16.h>
#include <math.h>

// ---------------- problem constants ----------------
#define SEQ   2048
#define DIMC  1024
#define HEADS 16
#define KVH   4
#define HD    64
#define KVDIM 256
#define WIN   64
#define NGLOB 32
#define TQ    32
#define SCALE 0.125f

// ---------------- scratch ----------------
__device__ float g_Q[SEQ * DIMC];
__device__ float g_K[SEQ * KVDIM];
__device__ float g_V[SEQ * KVDIM];
__device__ float g_A[SEQ * DIMC];
__device__ float g_Xc [SEQ * DIMC];        // tf32-rounded x
__device__ float g_WqT[DIMC * DIMC];       // transposed tf32 weights [N][K]
__device__ float g_WkT[KVDIM * DIMC];
__device__ float g_WvT[KVDIM * DIMC];
__device__ float g_WoT[DIMC * DIMC];

// ---------------- helpers ----------------
__device__ __forceinline__ unsigned f2tf32(float f) {
    unsigned r; asm("cvt.rna.tf32.f32 %0, %1;" : "=r"(r) : "f"(f)); return r;
}
__device__ __forceinline__ float tf32r(float f) { return __uint_as_float(f2tf32(f)); }

__device__ __forceinline__ void mma_tf32(float* c, const unsigned* a, const unsigned* b) {
    asm volatile(
        "mma.sync.aligned.m16n8k8.row.col.f32.tf32.tf32.f32 "
        "{%0,%1,%2,%3}, {%4,%5,%6,%7}, {%8,%9}, {%0,%1,%2,%3};"
        : "+f"(c[0]), "+f"(c[1]), "+f"(c[2]), "+f"(c[3])
        : "r"(a[0]), "r"(a[1]), "r"(a[2]), "r"(a[3]), "r"(b[0]), "r"(b[1]));
}

__device__ __forceinline__ void ldsm4(unsigned* r, unsigned saddr) {
    asm volatile("ldmatrix.sync.aligned.m8n8.x4.shared.b16 {%0,%1,%2,%3}, [%4];"
                 : "=r"(r[0]), "=r"(r[1]), "=r"(r[2]), "=r"(r[3]) : "r"(saddr));
}
__device__ __forceinline__ void ldsm2(unsigned* r, unsigned saddr) {
    asm volatile("ldmatrix.sync.aligned.m8n8.x2.shared.b16 {%0,%1}, [%2];"
                 : "=r"(r[0]), "=r"(r[1]) : "r"(saddr));
}

__device__ __forceinline__ void cp16(float* dst, const float* src) {
    unsigned s = (unsigned)__cvta_generic_to_shared(dst);
    asm volatile("cp.async.cg.shared.global [%0], [%1], 16;" :: "r"(s), "l"(src));
}
#define CP_COMMIT() asm volatile("cp.async.commit_group;")
#define CP_WAIT0()  asm volatile("cp.async.wait_group 0;")

__device__ __forceinline__ unsigned smem_u32(const void* p) {
    return (unsigned)__cvta_generic_to_shared(p);
}

// ---------------- GEMM geometry: 2-stage, 3 CTAs/SM ----------------
#define BM 128
#define BN 64
#define BK 32
#define RSTR 36
#define A_FL (BM * RSTR)
#define B_FL (BN * RSTR)
#define ST_FL (A_FL + B_FL)
#define ST_BYTES (ST_FL * 4)          // 27648
#define GEMM_SMEM (2 * ST_BYTES)      // 55296
#define NCH (DIMC / BK)               // 32

// =================================================================
// Convert: x elementwise tf32-round; weights -> transposed tf32 [N][K].
// =================================================================
__global__ __launch_bounds__(256)
void cvt_all(const float4* __restrict__ x, const float* __restrict__ wq,
             const float* __restrict__ wk, const float* __restrict__ wv,
             const float* __restrict__ wo,
             float4* __restrict__ xc, float* __restrict__ wqT,
             float* __restrict__ wkT, float* __restrict__ wvT,
             float* __restrict__ woT)
{
    __shared__ float s[32][33];
    const int tid = threadIdx.x;
    if (blockIdx.x < 2048) {
        int i = blockIdx.x * 256 + tid;
        float4 v = x[i];
        v.x = tf32r(v.x); v.y = tf32r(v.y); v.z = tf32r(v.z); v.w = tf32r(v.w);
        xc[i] = v;
        return;
    }
    int b = blockIdx.x - 2048;
    const float* W; float* WT; int N;
    if (b < 1024)       { W = wq; WT = wqT; N = DIMC; }
    else if (b < 1280)  { b -= 1024; W = wk; WT = wkT; N = KVDIM; }
    else if (b < 1536)  { b -= 1280; W = wv; WT = wvT; N = KVDIM; }
    else                { b -= 1536; W = wo; WT = woT; N = DIMC; }
    const int ntile = N / 32;
    const int n0 = (b % ntile) * 32;
    const int k0 = (b / ntile) * 32;
    const int c = tid & 31, r0 = tid >> 5;
#pragma unroll
    for (int rr = 0; rr < 4; rr++) {
        int r = r0 + rr * 8;
        s[r][c] = tf32r(W[(size_t)(k0 + r) * N + n0 + c]);
    }
    __syncthreads();
#pragma unroll
    for (int rr = 0; rr < 4; rr++) {
        int r = r0 + rr * 8;
        WT[(size_t)(n0 + r) * DIMC + k0 + c] = s[c][r];
    }
}

// =================================================================
// 128x64 tf32 MMA tile: ldmatrix feeds, 2-stage cp.async, 1 sync/chunk.
// =================================================================
__device__ __forceinline__ void mma_tile(const float* __restrict__ A,
                                         const float* __restrict__ BT,
                                         float* __restrict__ C,
                                         int ldc, int by, float* sm)
{
    const int tid  = threadIdx.x;
    const int lane = tid & 31, warp = tid >> 5;
    const int wm = (warp >> 1) * 32;
    const int wn = (warp & 1) * 32;
    const int grp = lane >> 2, ctg = lane & 3;

    float acc[2][4][4];
#pragma unroll
    for (int i = 0; i < 2; i++)
#pragma unroll
        for (int j = 0; j < 4; j++)
#pragma unroll
            for (int r = 0; r < 4; r++) acc[i][j][r] = 0.f;

    const float* Abase = A + (size_t)(by * BM) * DIMC;

    auto load_chunk = [&](int c, int s) {
        float* as = sm + s * ST_FL;
        float* bs = as + A_FL;
        const int k0 = c * BK;
#pragma unroll
        for (int i = 0; i < 4; i++) {
            int idx = tid + i * 256;
            int r = idx >> 3, g = idx & 7;
            cp16(as + r * RSTR + g * 4, Abase + (size_t)r * DIMC + k0 + g * 4);
        }
#pragma unroll
        for (int i = 0; i < 2; i++) {
            int idx = tid + i * 256;
            int n = idx >> 3, g = idx & 7;
            cp16(bs + n * RSTR + g * 4, BT + (size_t)n * DIMC + k0 + g * 4);
        }
    };

    const unsigned aOff = (unsigned)(((wm + (lane & 15)) * RSTR + (lane >> 4) * 4) * 4);
    const unsigned bOff = (unsigned)(A_FL * 4 +
        ((wn + ((lane >> 4) << 3) + (lane & 7)) * RSTR + ((lane >> 3) & 1) * 4) * 4);
    const unsigned sb = smem_u32(sm);

    load_chunk(0, 0); CP_COMMIT();

#pragma unroll 2
    for (int c = 0; c < NCH; c++) {
        const int s = c & 1;
        CP_WAIT0();          // chunk c resident
        __syncthreads();     // also: everyone finished computing chunk c-1
        if (c + 1 < NCH) {
            load_chunk(c + 1, s ^ 1);
            CP_COMMIT();
        }

        const unsigned stb = sb + (unsigned)(s * ST_BYTES);
        const unsigned aA = stb + aOff;
        const unsigned bA = stb + bOff;
#pragma unroll
        for (int ks = 0; ks < 4; ks++) {
            unsigned a0[4], a1[4], b0[4], b1[4];
            ldsm4(a0, aA + ks * 32);
            ldsm4(a1, aA + 2304 + ks * 32);
            ldsm4(b0, bA + ks * 32);
            ldsm4(b1, bA + 2304 + ks * 32);
            mma_tf32(acc[0][0], a0, &b0[0]);
            mma_tf32(acc[0][1], a0, &b0[2]);
            mma_tf32(acc[0][2], a0, &b1[0]);
            mma_tf32(acc[0][3], a0, &b1[2]);
            mma_tf32(acc[1][0], a1, &b0[0]);
            mma_tf32(acc[1][1], a1, &b0[2]);
            mma_tf32(acc[1][2], a1, &b1[0]);
            mma_tf32(acc[1][3], a1, &b1[2]);
        }
    }

#pragma unroll
    for (int mi = 0; mi < 2; mi++) {
        const int row = by * BM + wm + mi * 16 + grp;
#pragma unroll
        for (int ni = 0; ni < 4; ni++) {
            const int col = wn + ni * 8 + 2 * ctg;
            *(float2*)(C + (size_t)row * ldc + col) =
                make_float2(acc[mi][ni][0], acc[mi][ni][1]);
            *(float2*)(C + (size_t)(row + 8) * ldc + col) =
                make_float2(acc[mi][ni][2], acc[mi][ni][3]);
        }
    }
}

__global__ __launch_bounds__(256, 3)
void tf32_qkv(const float* __restrict__ Xc,
              const float* __restrict__ WqT, const float* __restrict__ WkT,
              const float* __restrict__ WvT,
              float* __restrict__ Q, float* __restrict__ Ko, float* __restrict__ Vo)
{
    extern __shared__ float sm[];
    const int bx = blockIdx.x;
    const float* BT; float* C; int ld;
    if (bx < 16)      { BT = WqT + (size_t)bx * 64 * DIMC;        C = Q  + bx * 64;        ld = DIMC;  }
    else if (bx < 20) { BT = WkT + (size_t)(bx - 16) * 64 * DIMC; C = Ko + (bx - 16) * 64; ld = KVDIM; }
    else              { BT = WvT + (size_t)(bx - 20) * 64 * DIMC; C = Vo + (bx - 20) * 64; ld = KVDIM; }
    mma_tile(Xc, BT, C, ld, blockIdx.y, sm);
}

__global__ __launch_bounds__(256, 3)
void tf32_wo(const float* __restrict__ Ac, const float* __restrict__ WoT,
             float* __restrict__ Out)
{
    extern __shared__ float sm[];
    mma_tile(Ac, WoT + (size_t)blockIdx.x * 64 * DIMC, Out + blockIdx.x * 64,
             DIMC, blockIdx.y, sm);
}

// =================================================================
// Tensorized attention (unchanged from R11). Grid (64,16), 256 thr, 92KB.
// =================================================================
#define AT_QS 0
#define AT_KL 2176
#define AT_KG 8704
#define AT_VT 10880
#define AT_P  19328
#define ATTN_SMEM (23552 * 4)

__global__ __launch_bounds__(256)
void attn_mma(const float* __restrict__ Q, const float* __restrict__ K,
              const float* __restrict__ V, float* __restrict__ O)
{
    extern __shared__ float sm[];
    const int h = blockIdx.y, kvh = h >> 2, q0 = blockIdx.x * TQ;
    const int tid = threadIdx.x, lane = tid & 31, warp = tid >> 5;
    const float slope = exp2f(-0.5f * (float)(h + 1));

    for (int i = tid; i < 32 * 16; i += 256) {
        int q = i >> 4, d4 = i & 15;
        float4 v = *(const float4*)&Q[(size_t)(q0 + q) * DIMC + h * HD + d4 * 4];
        v.x = tf32r(v.x); v.y = tf32r(v.y); v.z = tf32r(v.z); v.w = tf32r(v.w);
        *(float4*)&sm[AT_QS + q * 68 + d4 * 4] = v;
    }
    for (int i = tid; i < 96 * 16; i += 256) {
        int r = i >> 4, d4 = i & 15;
        int key = q0 - 64 + r;
        float4 v = make_float4(0.f, 0.f, 0.f, 0.f);
        if (key >= 0) {
            v = *(const float4*)&K[(size_t)key * KVDIM + kvh * HD + d4 * 4];
            v.x = tf32r(v.x); v.y = tf32r(v.y); v.z = tf32r(v.z); v.w = tf32r(v.w);
        }
        *(float4*)&sm[AT_KL + r * 68 + d4 * 4] = v;
    }
    for (int i = tid; i < 32 * 16; i += 256) {
        int g = i >> 4, d4 = i & 15;
        float4 v = *(const float4*)&K[(size_t)(g * WIN) * KVDIM + kvh * HD + d4 * 4];
        v.x = tf32r(v.x); v.y = tf32r(v.y); v.z = tf32r(v.z); v.w = tf32r(v.w);
        *(float4*)&sm[AT_KG + g * 68 + d4 * 4] = v;
    }
    for (int i = tid; i < 128 * 16; i += 256) {
        int col = i >> 4, d4 = i & 15;
        int key; bool valid;
        if (col < 96) { key = q0 - 64 + col; valid = (key >= 0); }
        else          { key = (col - 96) * WIN; valid = true; }
        float4 v = make_float4(0.f, 0.f, 0.f, 0.f);
        if (valid) {
            v = *(const float4*)&V[(size_t)key * KVDIM + kvh * HD + d4 * 4];
            v.x = tf32r(v.x); v.y = tf32r(v.y); v.z = tf32r(v.z); v.w = tf32r(v.w);
        }
        sm[AT_VT + (d4 * 4 + 0) * 132 + col] = v.x;
        sm[AT_VT + (d4 * 4 + 1) * 132 + col] = v.y;
        sm[AT_VT + (d4 * 4 + 2) * 132 + col] = v.z;
        sm[AT_VT + (d4 * 4 + 3) * 132 + col] = v.w;
    }
    __syncthreads();

    const unsigned sb = smem_u32(sm);
    const int m0  = (warp >> 2) * 16;
    const int wnl = (warp & 3) * 24;
    const int wng = (warp & 3) * 8;
    const int ln  = lane & 15;
    const int grp = lane >> 2, ctg = lane & 3;

    {
        const unsigned aQ  = sb + (unsigned)((AT_QS + (m0 + ln) * 68 + (lane >> 4) * 4) * 4);
        const unsigned bKl = sb + (unsigned)((AT_KL + (wnl + ((lane >> 4) << 3) + (lane & 7)) * 68 + ((lane >> 3) & 1) * 4) * 4);
        const unsigned bK2 = sb + (unsigned)((AT_KL + (wnl + 16 + (ln & 7)) * 68 + ((ln >> 3) & 1) * 4) * 4);
        const unsigned bKg = sb + (unsigned)((AT_KG + (wng + (ln & 7)) * 68 + ((ln >> 3) & 1) * 4) * 4);

        float accl[3][4], accg[4];
#pragma unroll
        for (int f = 0; f < 3; f++)
#pragma unroll
            for (int r = 0; r < 4; r++) accl[f][r] = 0.f;
#pragma unroll
        for (int r = 0; r < 4; r++) accg[r] = 0.f;

#pragma unroll
        for (int ks = 0; ks < 8; ks++) {
            unsigned a[4], b01[4], b2[2], bg[2];
            ldsm4(a, aQ + ks * 32);
            ldsm4(b01, bKl + ks * 32);
            ldsm2(b2, bK2 + ks * 32);
            ldsm2(bg, bKg + ks * 32);
            mma_tf32(accl[0], a, &b01[0]);
            mma_tf32(accl[1], a, &b01[2]);
            mma_tf32(accl[2], a, b2);
            mma_tf32(accg, a, bg);
        }
        const int row = m0 + grp;
#pragma unroll
        for (int f = 0; f < 3; f++) {
            int col = wnl + f * 8 + 2 * ctg;
            *(float2*)&sm[AT_P + row * 132 + col]       = make_float2(accl[f][0], accl[f][1]);
            *(float2*)&sm[AT_P + (row + 8) * 132 + col] = make_float2(accl[f][2], accl[f][3]);
        }
        int colg = 96 + wng + 2 * ctg;
        *(float2*)&sm[AT_P + row * 132 + colg]       = make_float2(accg[0], accg[1]);
        *(float2*)&sm[AT_P + (row + 8) * 132 + colg] = make_float2(accg[2], accg[3]);
    }
    __syncthreads();

    for (int q = warp * 4; q < warp * 4 + 4; q++) {
        float l[3]; bool vld[3];
        float m = -3.0e38f;
#pragma unroll
        for (int t = 0; t < 3; t++) {
            int r = lane + t * 32;
            vld[t] = (r >= q) && (r <= q + 64) && (q0 - 64 + r >= 0);
            l[t] = vld[t] ? sm[AT_P + q * 132 + r] * SCALE + (float)(r - q - 64) * slope
                          : -3.0e38f;
            m = fmaxf(m, l[t]);
        }
#pragma unroll
        for (int o = 16; o; o >>= 1) m = fmaxf(m, __shfl_xor_sync(~0u, m, o));
        float e[3], sum = 0.f;
#pragma unroll
        for (int t = 0; t < 3; t++) {
            e[t] = vld[t] ? __expf(l[t] - m) : 0.f;
            sum += e[t];
        }
#pragma unroll
        for (int o = 16; o; o >>= 1) sum += __shfl_xor_sync(~0u, sum, o);
        float inv = 1.f / sum;
#pragma unroll
        for (int t = 0; t < 3; t++)
            sm[AT_P + q * 132 + lane + t * 32] = tf32r(e[t] * inv);

        float gl = sm[AT_P + q * 132 + 96 + lane] * SCALE;
        float mg = gl;
#pragma unroll
        for (int o = 16; o; o >>= 1) mg = fmaxf(mg, __shfl_xor_sync(~0u, mg, o));
        float ge = __expf(gl - mg);
        float gs = ge;
#pragma unroll
        for (int o = 16; o; o >>= 1) gs += __shfl_xor_sync(~0u, gs, o);
        sm[AT_P + q * 132 + 96 + lane] = tf32r(ge / gs);
    }
    __syncthreads();

    {
        const int n0 = (warp & 3) * 16;
        const unsigned aP = sb + (unsigned)((AT_P + (m0 + ln) * 132 + (lane >> 4) * 4) * 4);
        const unsigned bV = sb + (unsigned)((AT_VT + (n0 + ((lane >> 4) << 3) + (lane & 7)) * 132 + ((lane >> 3) & 1) * 4) * 4);

        float acco[2][4];
#pragma unroll
        for (int f = 0; f < 2; f++)
#pragma unroll
            for (int r = 0; r < 4; r++) acco[f][r] = 0.f;

#pragma unroll
        for (int ks = 0; ks < 16; ks++) {
            unsigned a[4], b[4];
            ldsm4(a, aP + ks * 32);
            ldsm4(b, bV + ks * 32);
            mma_tf32(acco[0], a, &b[0]);
            mma_tf32(acco[1], a, &b[2]);
        }

        const int row = m0 + grp;
#pragma unroll
        for (int f = 0; f < 2; f++) {
            int col = h * HD + n0 + f * 8 + 2 * ctg;
            *(float2*)&O[(size_t)(q0 + row) * DIMC + col] =
                make_float2(tf32r(acco[f][0]), tf32r(acco[f][1]));
            *(float2*)&O[(size_t)(q0 + row + 8) * DIMC + col] =
                make_float2(tf32r(acco[f][2]), tf32r(acco[f][3]));
        }
    }
}

// =================================================================
extern "C" void kernel_launch(void* const* d_in, const int* in_sizes, int n_in,
                              void* d_out, int out_size)
{
    const float* x  = (const float*)d_in[0];
    const float* Wq = (const float*)d_in[1];
    const float* Wk = (const float*)d_in[2];
    const float* Wv = (const float*)d_in[3];
    const float* Wo = (const float*)d_in[4];
    float* out = (float*)d_out;

    float *gQ, *gK, *gV, *gA, *gXc, *gWqT, *gWkT, *gWvT, *gWoT;
    cudaGetSymbolAddress((void**)&gQ,  g_Q);
    cudaGetSymbolAddress((void**)&gK,  g_K);
    cudaGetSymbolAddress((void**)&gV,  g_V);
    cudaGetSymbolAddress((void**)&gA,  g_A);
    cudaGetSymbolAddress((void**)&gXc, g_Xc);
    cudaGetSymbolAddress((void**)&gWqT, g_WqT);
    cudaGetSymbolAddress((void**)&gWkT, g_WkT);
    cudaGetSymbolAddress((void**)&gWvT, g_WvT);
    cudaGetSymbolAddress((void**)&gWoT, g_WoT);

    cudaFuncSetAttribute(tf32_qkv, cudaFuncAttributeMaxDynamicSharedMemorySize, GEMM_SMEM);
    cudaFuncSetAttribute(tf32_wo,  cudaFuncAttributeMaxDynamicSharedMemorySize, GEMM_SMEM);
    cudaFuncSetAttribute(attn_mma, cudaFuncAttributeMaxDynamicSharedMemorySize, ATTN_SMEM);

    cvt_all<<<4608, 256>>>((const float4*)x, Wq, Wk, Wv, Wo,
                           (float4*)gXc, gWqT, gWkT, gWvT, gWoT);
    tf32_qkv<<<dim3(24, 16), 256, GEMM_SMEM>>>(gXc, gWqT, gWkT, gWvT, gQ, gK, gV);
    attn_mma<<<dim3(SEQ / TQ, HEADS), 256, ATTN_SMEM>>>(gQ, gK, gV, gA);
    tf32_wo<<<dim3(16, 16), 256, GEMM_SMEM>>>(gA, gWoT, out);
}